// round 5
// baseline (speedup 1.0000x reference)
#include <cuda_runtime.h>
#include <math.h>
#include <stdint.h>

// Problem dims (fixed by the dataset)
#define B_    2
#define L_    1024
#define DM    1024
#define DI    2048
#define NS    16
#define DTR   64
#define DC    4
#define NTOK  (B_ * L_)      // 2048 tokens
#define XDBLW 96             // DT_RANK + 2*N

// ---------------------------------------------------------------------------
// Scratch (static __device__ arrays -- allocation-free per harness rules)
// ---------------------------------------------------------------------------
__device__ float g_xz   [(size_t)NTOK * 2 * DI];
__device__ float g_xconv[(size_t)NTOK * DI];
__device__ float g_xdbl [(size_t)NTOK * XDBLW];
__device__ float g_delta[(size_t)NTOK * DI];
__device__ float g_ybuf [(size_t)NTOK * DI];
// prepped (tf32 + permuted/swizzled) operands
__device__ float g_hsP  [(size_t)NTOK * DM];      // A of GEMM1
__device__ float g_WinT [(size_t)(2 * DI) * DM];  // B^T of GEMM1
__device__ float g_xdP  [(size_t)NTOK * DTR];     // A of GEMM4
__device__ float g_WdtT [(size_t)DI * DTR];       // B^T of GEMM4
__device__ float g_ybP  [(size_t)NTOK * DI];      // A of GEMM6
__device__ float g_WoutT[(size_t)DM * DI];        // B^T of GEMM6

// ---------------------------------------------------------------------------
// Helpers
// ---------------------------------------------------------------------------
__device__ __forceinline__ float silu_f(float x) {
    return x / (1.0f + __expf(-x));
}
__device__ __forceinline__ float softplus_f(float x) {
    return (x > 20.0f) ? x : log1pf(__expf(x));
}
__device__ __forceinline__ float f2tf32f(float f) {
    uint32_t u;
    asm("cvt.rna.tf32.f32 %0, %1;\n" : "=r"(u) : "f"(f));
    return __uint_as_float(u);
}
__device__ __forceinline__ void mma_tf32(float* c,
                                         uint32_t a0, uint32_t a1, uint32_t a2, uint32_t a3,
                                         uint32_t b0, uint32_t b1) {
    asm volatile(
        "mma.sync.aligned.m16n8k8.row.col.f32.tf32.tf32.f32 "
        "{%0,%1,%2,%3}, {%4,%5,%6,%7}, {%8,%9}, {%0,%1,%2,%3};\n"
        : "+f"(c[0]), "+f"(c[1]), "+f"(c[2]), "+f"(c[3])
        : "r"(a0), "r"(a1), "r"(a2), "r"(a3), "r"(b0), "r"(b1));
}

#define CPA16(smp, gp) \
    asm volatile("cp.async.cg.shared.global [%0], [%1], 16;\n" :: "r"(smp), "l"(gp))
#define CPA_COMMIT()  asm volatile("cp.async.commit_group;\n")
#define CPA_WAIT1()   asm volatile("cp.async.wait_group 1;\n" ::: "memory")
#define CPA_WAIT0()   asm volatile("cp.async.wait_group 0;\n" ::: "memory")

// Permuted+swizzled column for logical k in row r:
//   within each 16-chunk: pos = 4*(k&3) + ((k>>2)&3)   (frag k-values contiguous)
//   4-float chunk XOR-swizzled by (r&3)                (bank-conflict-free LDS.128)
__device__ __forceinline__ int pcol(int k, int r) {
    return (k & ~15) + 4 * (((k) & 3) ^ (r & 3)) + ((k >> 2) & 3);
}

// ---------------------------------------------------------------------------
// Prep A: out[m][pcol(k,m)] = tf32(in[m][k]);  K = 1<<kbits
// ---------------------------------------------------------------------------
__global__ void prepA_kernel(const float* __restrict__ in, float* __restrict__ out,
                             int MK, int kbits, int ldin)
{
    int idx = blockIdx.x * blockDim.x + threadIdx.x;
    if (idx >= MK) return;
    int m = idx >> kbits;
    int k = idx & ((1 << kbits) - 1);
    out[((size_t)m << kbits) + pcol(k, m)] = f2tf32f(in[(size_t)m * ldin + k]);
}

// ---------------------------------------------------------------------------
// Prep B^T: out[n][pcol(k,n)] = tf32(W[k][n]).  W is (K, N) row-major.
// ---------------------------------------------------------------------------
__global__ void prepBt_kernel(const float* __restrict__ W, float* __restrict__ out,
                              int K, int N)
{
    __shared__ float tile[32][33];
    const int k0 = blockIdx.y * 32;
    const int n0 = blockIdx.x * 32;
    const int tx = threadIdx.x, ty = threadIdx.y;   // 32 x 8

    #pragma unroll
    for (int j = 0; j < 32; j += 8)
        tile[ty + j][tx] = W[(size_t)(k0 + ty + j) * N + n0 + tx];
    __syncthreads();

    const int k = k0 + tx;
    #pragma unroll
    for (int j = 0; j < 32; j += 8) {
        const int n = n0 + ty + j;
        out[(size_t)n * K + pcol(k, n)] = f2tf32f(tile[tx][ty + j]);
    }
}

// ---------------------------------------------------------------------------
// TF32 tensor-core GEMM on prepped operands.
// C[M,N] = A[M,K] @ B[K,N];  A prepped [M][K], Bt prepped [N][K].
// Block 128x128, BK=16, 256 threads, warp tile 64x32.
// Inner loop: 12 LDS.128 + 32 HMMA per warp per tile; cp.async double-buffer.
// EPI: 0 = plain store, 1 = softplus(acc + bias[col])
// ---------------------------------------------------------------------------
template <int EPI>
__global__ void __launch_bounds__(256, 2)
tgemm(const float* __restrict__ A, const float* __restrict__ Bt,
      float* __restrict__ C, int K, int ldc, const float* __restrict__ bias)
{
    __shared__ float As[2][128][16];
    __shared__ float Bs[2][128][16];

    const int tid  = threadIdx.x;
    const int bm   = blockIdx.y * 128;
    const int bn   = blockIdx.x * 128;
    const int lane = tid & 31;
    const int wid  = tid >> 5;
    const int wm   = (wid & 1) * 64;
    const int wn   = (wid >> 1) * 32;
    const int g    = lane >> 2;
    const int t    = lane & 3;

    // staging: each thread copies 2 contiguous 16B chunks of one A row + one B row
    const int r0 = tid >> 1;
    const int c0 = (tid & 1) * 8;

    const float* Ag = A  + (size_t)(bm + r0) * K + c0;
    const float* Bg = Bt + (size_t)(bn + r0) * K + c0;

    const uint32_t sA = (uint32_t)__cvta_generic_to_shared(&As[0][0][0]);
    const uint32_t sB = (uint32_t)__cvta_generic_to_shared(&Bs[0][0][0]);
    const uint32_t BUFB = 128 * 16 * 4;   // bytes per buffer
    const uint32_t stgA = sA + (uint32_t)(r0 * 16 + c0) * 4;
    const uint32_t stgB = sB + (uint32_t)(r0 * 16 + c0) * 4;

#define STAGE(bf, kk)                                   \
    {                                                   \
        CPA16(stgA + (bf) * BUFB,      Ag + (kk));      \
        CPA16(stgA + (bf) * BUFB + 16, Ag + (kk) + 4);  \
        CPA16(stgB + (bf) * BUFB,      Bg + (kk));      \
        CPA16(stgB + (bf) * BUFB + 16, Bg + (kk) + 4);  \
        CPA_COMMIT();                                   \
    }

    // fragment base pointers (swizzled column)
    const int colf = 4 * (t ^ (g & 3));
    const float* fA = &As[0][wm + g][colf];
    const float* fB = &Bs[0][wn + g][colf];

    float acc[4][4][4];
    #pragma unroll
    for (int mi = 0; mi < 4; mi++)
        #pragma unroll
        for (int ni = 0; ni < 4; ni++)
            #pragma unroll
            for (int r = 0; r < 4; r++) acc[mi][ni][r] = 0.0f;

    const int nIter = K / 16;
    STAGE(0, 0);

    int buf = 0;
    for (int it = 0; it < nIter; ++it) {
        if (it + 1 < nIter) {
            STAGE(buf ^ 1, (it + 1) * 16);
            CPA_WAIT1();
        } else {
            CPA_WAIT0();
        }
        __syncthreads();

        const float* pa = fA + buf * (BUFB / 4);
        const float* pb = fB + buf * (BUFB / 4);

        uint4 a0[4], a1[4], bv[4];
        #pragma unroll
        for (int mi = 0; mi < 4; mi++) {
            a0[mi] = *(const uint4*)(pa + mi * 256);        // row wm+mi*16+g
            a1[mi] = *(const uint4*)(pa + mi * 256 + 128);  // row +8
        }
        #pragma unroll
        for (int ni = 0; ni < 4; ni++)
            bv[ni] = *(const uint4*)(pb + ni * 128);        // row wn+ni*8+g

        #pragma unroll
        for (int mi = 0; mi < 4; mi++)
            #pragma unroll
            for (int ni = 0; ni < 4; ni++)
                mma_tf32(acc[mi][ni], a0[mi].x, a1[mi].x, a0[mi].y, a1[mi].y,
                         bv[ni].x, bv[ni].y);
        #pragma unroll
        for (int mi = 0; mi < 4; mi++)
            #pragma unroll
            for (int ni = 0; ni < 4; ni++)
                mma_tf32(acc[mi][ni], a0[mi].z, a1[mi].z, a0[mi].w, a1[mi].w,
                         bv[ni].z, bv[ni].w);

        buf ^= 1;
        __syncthreads();
    }

    // epilogue
    #pragma unroll
    for (int mi = 0; mi < 4; mi++) {
        #pragma unroll
        for (int ni = 0; ni < 4; ni++) {
            const int row = bm + wm + mi * 16 + g;
            const int col = bn + wn + ni * 8 + 2 * t;
            float v0 = acc[mi][ni][0], v1 = acc[mi][ni][1];
            float v2 = acc[mi][ni][2], v3 = acc[mi][ni][3];
            if (EPI == 1) {
                const float b0v = bias[col], b1v = bias[col + 1];
                v0 = softplus_f(v0 + b0v);
                v1 = softplus_f(v1 + b1v);
                v2 = softplus_f(v2 + b0v);
                v3 = softplus_f(v3 + b1v);
            }
            *(float2*)(C + (size_t)row * ldc + col)       = make_float2(v0, v1);
            *(float2*)(C + (size_t)(row + 8) * ldc + col) = make_float2(v2, v3);
        }
    }
#undef STAGE
}

// ---------------------------------------------------------------------------
// Causal depthwise conv (k=4) + SiLU on the x half of xz
// ---------------------------------------------------------------------------
__global__ void conv_silu_kernel(const float* __restrict__ xz,
                                 const float* __restrict__ kw,
                                 const float* __restrict__ kb,
                                 float* __restrict__ out)
{
    int idx = blockIdx.x * blockDim.x + threadIdx.x;
    if (idx >= NTOK * DI) return;
    int d = idx & (DI - 1);
    int t = idx >> 11;
    int l = t & (L_ - 1);

    float acc = kb[d];
    #pragma unroll
    for (int i = 0; i < DC; i++) {
        int ls = l - (DC - 1) + i;
        if (ls >= 0)
            acc = fmaf(xz[(size_t)(t - (DC - 1) + i) * (2 * DI) + d],
                       kw[i * DI + d], acc);
    }
    out[idx] = silu_f(acc);
}

// ---------------------------------------------------------------------------
// x_dbl = xconv @ Wx   (NTOK x 96, K=2048). 4 token rows per block.
// ---------------------------------------------------------------------------
#define XR 4
__global__ void __launch_bounds__(96)
xdbl_kernel(const float* __restrict__ xc, const float* __restrict__ Wx,
            float* __restrict__ out)
{
    __shared__ float sh[XR][DI];
    const int row0 = blockIdx.x * XR;
    const int col  = threadIdx.x;
    for (int i = col; i < XR * DI; i += 96)
        ((float*)sh)[i] = xc[(size_t)row0 * DI + i];
    __syncthreads();

    float acc[XR] = {0.0f, 0.0f, 0.0f, 0.0f};
    for (int k = 0; k < DI; k++) {
        float w = Wx[(size_t)k * XDBLW + col];
        #pragma unroll
        for (int r = 0; r < XR; r++)
            acc[r] = fmaf(sh[r][k], w, acc[r]);
    }
    #pragma unroll
    for (int r = 0; r < XR; r++)
        out[(size_t)(row0 + r) * XDBLW + col] = acc[r];
}

// ---------------------------------------------------------------------------
// Selective scan. One thread per (channel, state-n); 16-lane groups reduce y.
// ---------------------------------------------------------------------------
__global__ void __launch_bounds__(256)
scan_kernel(const float* __restrict__ delta, const float* __restrict__ u,
            const float* __restrict__ xdbl,  const float* __restrict__ xz,
            const float* __restrict__ A_log, const float* __restrict__ Dskip,
            float* __restrict__ y)
{
    const int tid = threadIdx.x;
    const int grp = tid >> 4;
    const int n   = tid & 15;
    const int c   = blockIdx.x * 16 + grp;
    const int b   = c >> 11;
    const int d   = c & (DI - 1);

    const float An = -__expf(A_log[d * NS + n]);
    const float Dd = Dskip[d];

    const float* drow = delta + (size_t)b * L_ * DI + d;
    const float* urow = u     + (size_t)b * L_ * DI + d;
    const float* zrow = xz    + (size_t)b * L_ * (2 * DI) + DI + d;
    const float* brow = xdbl  + (size_t)b * L_ * XDBLW + DTR + n;
    float*       yrow = y     + (size_t)b * L_ * DI + d;

    float x = 0.0f;
    for (int l = 0; l < L_; ++l) {
        float dv = drow[(size_t)l * DI];
        float uv = urow[(size_t)l * DI];
        float Bn = brow[(size_t)l * XDBLW];
        float Cn = brow[(size_t)l * XDBLW + NS];

        float dA = __expf(dv * An);
        x = fmaf(dA, x, dv * Bn * uv);

        float v = x * Cn;
        v += __shfl_xor_sync(0xffffffffu, v, 1, 16);
        v += __shfl_xor_sync(0xffffffffu, v, 2, 16);
        v += __shfl_xor_sync(0xffffffffu, v, 4, 16);
        v += __shfl_xor_sync(0xffffffffu, v, 8, 16);

        if (n == 0) {
            float zv = zrow[(size_t)l * (2 * DI)];
            yrow[(size_t)l * DI] = (v + uv * Dd) * silu_f(zv);
        }
    }
}

// ---------------------------------------------------------------------------
// Launch
// ---------------------------------------------------------------------------
extern "C" void kernel_launch(void* const* d_in, const int* in_sizes, int n_in,
                              void* d_out, int out_size)
{
    const float* hs      = (const float*)d_in[0];
    const float* Win     = (const float*)d_in[1];
    const float* Wx      = (const float*)d_in[2];
    const float* Wdt     = (const float*)d_in[3];
    const float* dt_bias = (const float*)d_in[4];
    const float* Wout    = (const float*)d_in[5];
    const float* dwk     = (const float*)d_in[6];
    const float* dwb     = (const float*)d_in[7];
    const float* A_log   = (const float*)d_in[8];
    const float* Dskip   = (const float*)d_in[9];
    float* out = (float*)d_out;

    float *xz, *xc, *xd, *dl, *yb;
    float *hsP, *WinT, *xdP, *WdtT, *ybP, *WoutT;
    cudaGetSymbolAddress((void**)&xz,   g_xz);
    cudaGetSymbolAddress((void**)&xc,   g_xconv);
    cudaGetSymbolAddress((void**)&xd,   g_xdbl);
    cudaGetSymbolAddress((void**)&dl,   g_delta);
    cudaGetSymbolAddress((void**)&yb,   g_ybuf);
    cudaGetSymbolAddress((void**)&hsP,  g_hsP);
    cudaGetSymbolAddress((void**)&WinT, g_WinT);
    cudaGetSymbolAddress((void**)&xdP,  g_xdP);
    cudaGetSymbolAddress((void**)&WdtT, g_WdtT);
    cudaGetSymbolAddress((void**)&ybP,  g_ybP);
    cudaGetSymbolAddress((void**)&WoutT, g_WoutT);

    // --- prep passes for operands available up-front ---
    prepA_kernel<<<(NTOK * DM) / 256, 256>>>(hs, hsP, NTOK * DM, 10, DM);
    prepBt_kernel<<<dim3((2 * DI) / 32, DM / 32), dim3(32, 8)>>>(Win, WinT, DM, 2 * DI);
    prepBt_kernel<<<dim3(DI / 32, DTR / 32), dim3(32, 8)>>>(Wdt, WdtT, DTR, DI);
    prepBt_kernel<<<dim3(DM / 32, DI / 32), dim3(32, 8)>>>(Wout, WoutT, DI, DM);

    // 1) xz = hidden @ Win            (2048 x 4096, K=1024)
    tgemm<0><<<dim3(4096 / 128, 2048 / 128), 256>>>(
        hsP, WinT, xz, DM, 2 * DI, nullptr);

    // 2) depthwise causal conv + silu on x half
    conv_silu_kernel<<<(NTOK * DI + 255) / 256, 256>>>(xz, dwk, dwb, xc);

    // 3) x_dbl = xconv @ Wx           (2048 x 96, K=2048)
    xdbl_kernel<<<NTOK / XR, 96>>>(xc, Wx, xd);

    // 4) delta = softplus(dt @ Wdt + dt_bias)   (2048 x 2048, K=64)
    prepA_kernel<<<(NTOK * DTR) / 256, 256>>>(xd, xdP, NTOK * DTR, 6, XDBLW);
    tgemm<1><<<dim3(2048 / 128, 2048 / 128), 256>>>(
        xdP, WdtT, dl, DTR, DI, dt_bias);

    // 5) selective scan (+skip, *silu(z))
    scan_kernel<<<(B_ * DI) / 16, 256>>>(dl, xc, xd, xz, A_log, Dskip, yb);

    // 6) out = y @ Wout               (2048 x 1024, K=2048)
    prepA_kernel<<<(NTOK * DI) / 256, 256>>>(yb, ybP, NTOK * DI, 11, DI);
    tgemm<0><<<dim3(1024 / 128, 2048 / 128), 256>>>(
        ybP, WoutT, out, DI, DM, nullptr);
}

// round 9
// speedup vs baseline: 1.3422x; 1.3422x over previous
#include <cuda_runtime.h>
#include <cuda_fp16.h>
#include <math.h>
#include <stdint.h>

// Problem dims (fixed by the dataset)
#define B_    2
#define L_    1024
#define DM    1024
#define DI    2048
#define NS    16
#define DTR   64
#define DC    4
#define NTOK  (B_ * L_)      // 2048 tokens
#define XDBLW 96             // DT_RANK + 2*N

// ---------------------------------------------------------------------------
// Scratch (static __device__ arrays -- allocation-free per harness rules)
// ---------------------------------------------------------------------------
__device__ float  g_xz   [(size_t)NTOK * 2 * DI];
__device__ float  g_xconv[(size_t)NTOK * DI];
__device__ float  g_xdbl [(size_t)NTOK * XDBLW];
__device__ float  g_delta[(size_t)NTOK * DI];
__device__ float  g_ybuf [(size_t)NTOK * DI];
// fp16 operands for the tensor-core GEMMs
__device__ __half g_hsH  [(size_t)NTOK * DM];      // A of GEMM1 [M,K]
__device__ __half g_WinTH[(size_t)(2 * DI) * DM];  // B^T of GEMM1 [N,K]
__device__ __half g_xdH  [(size_t)NTOK * DTR];     // A of GEMM4
__device__ __half g_WdtTH[(size_t)DI * DTR];       // B^T of GEMM4
__device__ __half g_ybH  [(size_t)NTOK * DI];      // A of GEMM6
__device__ __half g_WoutTH[(size_t)DM * DI];       // B^T of GEMM6

// ---------------------------------------------------------------------------
// Helpers
// ---------------------------------------------------------------------------
__device__ __forceinline__ float silu_f(float x) {
    return x / (1.0f + __expf(-x));
}
__device__ __forceinline__ float softplus_f(float x) {
    return (x > 20.0f) ? x : log1pf(__expf(x));
}

#define CPA16(smp, gp) \
    asm volatile("cp.async.cg.shared.global [%0], [%1], 16;\n" :: "r"(smp), "l"(gp))
#define CPA_COMMIT()  asm volatile("cp.async.commit_group;\n")
#define CPA_WAIT1()   asm volatile("cp.async.wait_group 1;\n" ::: "memory")
#define CPA_WAIT0()   asm volatile("cp.async.wait_group 0;\n" ::: "memory")

__device__ __forceinline__ uint32_t smem_u32(const void* p) {
    uint32_t a;
    asm("{ .reg .u64 t; cvta.to.shared.u64 t, %1; cvt.u32.u64 %0, t; }"
        : "=r"(a) : "l"(p));
    return a;
}

__device__ __forceinline__ void mma_f16(float* c,
                                        uint32_t a0, uint32_t a1, uint32_t a2, uint32_t a3,
                                        uint32_t b0, uint32_t b1) {
    asm volatile(
        "mma.sync.aligned.m16n8k16.row.col.f32.f16.f16.f32 "
        "{%0,%1,%2,%3}, {%4,%5,%6,%7}, {%8,%9}, {%0,%1,%2,%3};\n"
        : "+f"(c[0]), "+f"(c[1]), "+f"(c[2]), "+f"(c[3])
        : "r"(a0), "r"(a1), "r"(a2), "r"(a3), "r"(b0), "r"(b1));
}

// ---------------------------------------------------------------------------
// FP16 tensor-core GEMM: C[M,N] = A[M,K] @ Bt[N,K]^T, fp32 accumulate.
// A: [M][K] half row-major; Bt: [N][K] half row-major (i.e. B transposed).
// Block tile 128x128, K-tile 16, 256 threads (8 warps, warp tile 64x32).
// cp.async double-buffered. One m16n8k16 mma per (mi,ni) per K-tile.
// EPI: 0 = plain store, 1 = softplus(acc + bias[col])
// ---------------------------------------------------------------------------
template <int EPI>
__global__ void __launch_bounds__(256)
tgemm_h(const __half* __restrict__ A, const __half* __restrict__ Bt,
        float* __restrict__ C, int K, int ldc, const float* __restrict__ bias)
{
    __shared__ __align__(16) __half As[2][128][24];  // 24-half row stride: conflict-free
    __shared__ __align__(16) __half Bs[2][128][24];

    const int tid  = threadIdx.x;
    const int bm   = blockIdx.y * 128;
    const int bn   = blockIdx.x * 128;
    const int lane = tid & 31;
    const int wid  = tid >> 5;
    const int wm   = (wid & 1) * 64;
    const int wn   = (wid >> 1) * 32;
    const int g    = lane >> 2;          // 0..7
    const int t    = lane & 3;           // 0..3

    // staging: 256 chunks (128 rows x 2 x 16B) per operand; 1 chunk/thread each
    const int r   = tid >> 1;
    const int cch = tid & 1;

    const __half* Ag = A  + (size_t)(bm + r) * K + cch * 8;
    const __half* Bg = Bt + (size_t)(bn + r) * K + cch * 8;

    const uint32_t ABUFB = 128 * 24 * 2;  // bytes per buffer
    const uint32_t stA = smem_u32(&As[0][r][cch * 8]);
    const uint32_t stB = smem_u32(&Bs[0][r][cch * 8]);

#define STAGE(kt, bf)                                  \
    {                                                  \
        CPA16(stA + (bf) * ABUFB, Ag + (size_t)(kt) * 16); \
        CPA16(stB + (bf) * ABUFB, Bg + (size_t)(kt) * 16); \
        CPA_COMMIT();                                  \
    }

    float acc[4][4][4];
    #pragma unroll
    for (int mi = 0; mi < 4; mi++)
        #pragma unroll
        for (int ni = 0; ni < 4; ni++)
            #pragma unroll
            for (int q = 0; q < 4; q++) acc[mi][ni][q] = 0.0f;

    const int nIter = K / 16;
    STAGE(0, 0);

    int buf = 0;
    for (int it = 0; it < nIter; ++it) {
        if (it + 1 < nIter) {
            STAGE(it + 1, buf ^ 1);
            CPA_WAIT1();
        } else {
            CPA_WAIT0();
        }
        __syncthreads();

        uint32_t a0[4], a1[4], a2[4], a3[4], b0[4], b1[4];
        #pragma unroll
        for (int mi = 0; mi < 4; mi++) {
            const int m0 = wm + mi * 16;
            a0[mi] = *(const uint32_t*)&As[buf][m0 + g][2 * t];
            a1[mi] = *(const uint32_t*)&As[buf][m0 + g + 8][2 * t];
            a2[mi] = *(const uint32_t*)&As[buf][m0 + g][2 * t + 8];
            a3[mi] = *(const uint32_t*)&As[buf][m0 + g + 8][2 * t + 8];
        }
        #pragma unroll
        for (int ni = 0; ni < 4; ni++) {
            const int n0 = wn + ni * 8 + g;
            b0[ni] = *(const uint32_t*)&Bs[buf][n0][2 * t];
            b1[ni] = *(const uint32_t*)&Bs[buf][n0][2 * t + 8];
        }
        #pragma unroll
        for (int mi = 0; mi < 4; mi++)
            #pragma unroll
            for (int ni = 0; ni < 4; ni++)
                mma_f16(acc[mi][ni], a0[mi], a1[mi], a2[mi], a3[mi],
                        b0[ni], b1[ni]);

        buf ^= 1;
        __syncthreads();
    }

    // epilogue: d-frag mapping — (g, 2t/2t+1) and (g+8, ...)
    #pragma unroll
    for (int mi = 0; mi < 4; mi++) {
        #pragma unroll
        for (int ni = 0; ni < 4; ni++) {
            const int row = bm + wm + mi * 16 + g;
            const int col = bn + wn + ni * 8 + 2 * t;
            float v0 = acc[mi][ni][0], v1 = acc[mi][ni][1];
            float v2 = acc[mi][ni][2], v3 = acc[mi][ni][3];
            if (EPI == 1) {
                const float c0 = bias[col], c1 = bias[col + 1];
                v0 = softplus_f(v0 + c0);
                v1 = softplus_f(v1 + c1);
                v2 = softplus_f(v2 + c0);
                v3 = softplus_f(v3 + c1);
            }
            *(float2*)(C + (size_t)row * ldc + col)       = make_float2(v0, v1);
            *(float2*)(C + (size_t)(row + 8) * ldc + col) = make_float2(v2, v3);
        }
    }
#undef STAGE
}

// ---------------------------------------------------------------------------
// Prep A -> half: out[m][k] = half(in[m*ldin + k]); processes 2 k's per thread
// ---------------------------------------------------------------------------
__global__ void prepA_h(const float* __restrict__ in, __half* __restrict__ out,
                        int MKhalf, int kbits, int ldin)
{
    int idx = blockIdx.x * blockDim.x + threadIdx.x;   // pair index
    if (idx >= MKhalf) return;
    int e  = idx * 2;
    int m  = e >> kbits;
    int k  = e & ((1 << kbits) - 1);
    const float* p = in + (size_t)m * ldin + k;
    ((__half2*)out)[idx] = __floats2half2_rn(p[0], p[1]);
}

// ---------------------------------------------------------------------------
// Prep B^T -> half: out[n][k] = half(W[k][n]).  W is (K, N) row-major.
// ---------------------------------------------------------------------------
__global__ void prepBt_h(const float* __restrict__ W, __half* __restrict__ out,
                         int K, int N)
{
    __shared__ float tile[32][33];
    const int k0 = blockIdx.y * 32;
    const int n0 = blockIdx.x * 32;
    const int tx = threadIdx.x, ty = threadIdx.y;   // 32 x 8

    #pragma unroll
    for (int j = 0; j < 32; j += 8)
        tile[ty + j][tx] = W[(size_t)(k0 + ty + j) * N + n0 + tx];
    __syncthreads();

    #pragma unroll
    for (int j = 0; j < 32; j += 8)
        out[(size_t)(n0 + ty + j) * K + k0 + tx] = __float2half(tile[tx][ty + j]);
}

// ---------------------------------------------------------------------------
// Causal depthwise conv (k=4) + SiLU on the x half of xz
// ---------------------------------------------------------------------------
__global__ void conv_silu_kernel(const float* __restrict__ xz,
                                 const float* __restrict__ kw,
                                 const float* __restrict__ kb,
                                 float* __restrict__ out)
{
    int idx = blockIdx.x * blockDim.x + threadIdx.x;
    if (idx >= NTOK * DI) return;
    int d = idx & (DI - 1);
    int t = idx >> 11;
    int l = t & (L_ - 1);

    float acc = kb[d];
    #pragma unroll
    for (int i = 0; i < DC; i++) {
        int ls = l - (DC - 1) + i;
        if (ls >= 0)
            acc = fmaf(xz[(size_t)(t - (DC - 1) + i) * (2 * DI) + d],
                       kw[i * DI + d], acc);
    }
    out[idx] = silu_f(acc);
}

// ---------------------------------------------------------------------------
// x_dbl = xconv @ Wx   (NTOK x 96, K=2048). 4 token rows per block.
// ---------------------------------------------------------------------------
#define XR 4
__global__ void __launch_bounds__(96)
xdbl_kernel(const float* __restrict__ xc, const float* __restrict__ Wx,
            float* __restrict__ out)
{
    __shared__ float sh[XR][DI];
    const int row0 = blockIdx.x * XR;
    const int col  = threadIdx.x;
    for (int i = col; i < XR * DI; i += 96)
        ((float*)sh)[i] = xc[(size_t)row0 * DI + i];
    __syncthreads();

    float acc[XR] = {0.0f, 0.0f, 0.0f, 0.0f};
    for (int k = 0; k < DI; k++) {
        float w = Wx[(size_t)k * XDBLW + col];
        #pragma unroll
        for (int r = 0; r < XR; r++)
            acc[r] = fmaf(sh[r][k], w, acc[r]);
    }
    #pragma unroll
    for (int r = 0; r < XR; r++)
        out[(size_t)(row0 + r) * XDBLW + col] = acc[r];
}

// ---------------------------------------------------------------------------
// Selective scan with load prefetch (next token's loads issued before the
// serial exp/fma chain of the current token). One thread per (channel, n);
// 16-lane groups reduce y over the state dim.
// ---------------------------------------------------------------------------
__global__ void __launch_bounds__(256)
scan_kernel(const float* __restrict__ delta, const float* __restrict__ u,
            const float* __restrict__ xdbl,  const float* __restrict__ xz,
            const float* __restrict__ A_log, const float* __restrict__ Dskip,
            float* __restrict__ y)
{
    const int tid = threadIdx.x;
    const int grp = tid >> 4;
    const int n   = tid & 15;
    const int c   = blockIdx.x * 16 + grp;
    const int b   = c >> 11;
    const int d   = c & (DI - 1);

    const float An = -__expf(A_log[d * NS + n]);
    const float Dd = Dskip[d];

    const float* drow = delta + (size_t)b * L_ * DI + d;
    const float* urow = u     + (size_t)b * L_ * DI + d;
    const float* zrow = xz    + (size_t)b * L_ * (2 * DI) + DI + d;
    const float* brow = xdbl  + (size_t)b * L_ * XDBLW + DTR + n;
    float*       yrow = y     + (size_t)b * L_ * DI + d;

    float x = 0.0f;
    float dv = drow[0];
    float uv = urow[0];
    float Bn = brow[0];
    float Cn = brow[NS];

#define SCAN_STEP(l)                                                        \
    {                                                                       \
        float dA = __expf(dv * An);                                         \
        x = fmaf(dA, x, dv * Bn * uv);                                      \
        float v = x * Cn;                                                   \
        v += __shfl_xor_sync(0xffffffffu, v, 1, 16);                        \
        v += __shfl_xor_sync(0xffffffffu, v, 2, 16);                        \
        v += __shfl_xor_sync(0xffffffffu, v, 4, 16);                        \
        v += __shfl_xor_sync(0xffffffffu, v, 8, 16);                        \
        if (n == 0) {                                                       \
            float zv = zrow[(size_t)(l) * (2 * DI)];                        \
            yrow[(size_t)(l) * DI] = (v + uv * Dd) * silu_f(zv);            \
        }                                                                   \
    }

    for (int l = 0; l < L_ - 1; ++l) {
        // prefetch next token (independent of the serial chain)
        float dv2 = drow[(size_t)(l + 1) * DI];
        float uv2 = urow[(size_t)(l + 1) * DI];
        float Bn2 = brow[(size_t)(l + 1) * XDBLW];
        float Cn2 = brow[(size_t)(l + 1) * XDBLW + NS];
        SCAN_STEP(l);
        dv = dv2; uv = uv2; Bn = Bn2; Cn = Cn2;
    }
    SCAN_STEP(L_ - 1);
#undef SCAN_STEP
}

// ---------------------------------------------------------------------------
// Launch
// ---------------------------------------------------------------------------
extern "C" void kernel_launch(void* const* d_in, const int* in_sizes, int n_in,
                              void* d_out, int out_size)
{
    const float* hs      = (const float*)d_in[0];
    const float* Win     = (const float*)d_in[1];
    const float* Wx      = (const float*)d_in[2];
    const float* Wdt     = (const float*)d_in[3];
    const float* dt_bias = (const float*)d_in[4];
    const float* Wout    = (const float*)d_in[5];
    const float* dwk     = (const float*)d_in[6];
    const float* dwb     = (const float*)d_in[7];
    const float* A_log   = (const float*)d_in[8];
    const float* Dskip   = (const float*)d_in[9];
    float* out = (float*)d_out;

    float  *xz, *xc, *xd, *dl, *yb;
    __half *hsH, *WinTH, *xdH, *WdtTH, *ybH, *WoutTH;
    cudaGetSymbolAddress((void**)&xz,     g_xz);
    cudaGetSymbolAddress((void**)&xc,     g_xconv);
    cudaGetSymbolAddress((void**)&xd,     g_xdbl);
    cudaGetSymbolAddress((void**)&dl,     g_delta);
    cudaGetSymbolAddress((void**)&yb,     g_ybuf);
    cudaGetSymbolAddress((void**)&hsH,    g_hsH);
    cudaGetSymbolAddress((void**)&WinTH,  g_WinTH);
    cudaGetSymbolAddress((void**)&xdH,    g_xdH);
    cudaGetSymbolAddress((void**)&WdtTH,  g_WdtTH);
    cudaGetSymbolAddress((void**)&ybH,    g_ybH);
    cudaGetSymbolAddress((void**)&WoutTH, g_WoutTH);

    // --- prep fp16 operands available up-front ---
    prepA_h<<<(NTOK * DM / 2) / 256, 256>>>(hs, hsH, NTOK * DM / 2, 10, DM);
    prepBt_h<<<dim3((2 * DI) / 32, DM / 32), dim3(32, 8)>>>(Win, WinTH, DM, 2 * DI);
    prepBt_h<<<dim3(DI / 32, DTR / 32), dim3(32, 8)>>>(Wdt, WdtTH, DTR, DI);
    prepBt_h<<<dim3(DM / 32, DI / 32), dim3(32, 8)>>>(Wout, WoutTH, DI, DM);

    // 1) xz = hidden @ Win            (2048 x 4096, K=1024)
    tgemm_h<0><<<dim3(4096 / 128, 2048 / 128), 256>>>(
        hsH, WinTH, xz, DM, 2 * DI, nullptr);

    // 2) depthwise causal conv + silu on x half
    conv_silu_kernel<<<(NTOK * DI + 255) / 256, 256>>>(xz, dwk, dwb, xc);

    // 3) x_dbl = xconv @ Wx           (2048 x 96, K=2048)
    xdbl_kernel<<<NTOK / XR, 96>>>(xc, Wx, xd);

    // 4) delta = softplus(dt @ Wdt + dt_bias)   (2048 x 2048, K=64)
    prepA_h<<<(NTOK * DTR / 2) / 256, 256>>>(xd, xdH, NTOK * DTR / 2, 6, XDBLW);
    tgemm_h<1><<<dim3(2048 / 128, 2048 / 128), 256>>>(
        xdH, WdtTH, dl, DTR, DI, dt_bias);

    // 5) selective scan (+skip, *silu(z))
    scan_kernel<<<(B_ * DI) / 16, 256>>>(dl, xc, xd, xz, A_log, Dskip, yb);

    // 6) out = y @ Wout               (2048 x 1024, K=2048)
    prepA_h<<<(NTOK * DI / 2) / 256, 256>>>(yb, ybH, NTOK * DI / 2, 11, DI);
    tgemm_h<0><<<dim3(1024 / 128, 2048 / 128), 256>>>(
        ybH, WoutTH, out, DI, DM, nullptr);
}

// round 10
// speedup vs baseline: 1.4845x; 1.1060x over previous
#include <cuda_runtime.h>
#include <cuda_fp16.h>
#include <math.h>
#include <stdint.h>

// Problem dims (fixed by the dataset)
#define B_    2
#define L_    1024
#define DM    1024
#define DI    2048
#define NS    16
#define DTR   64
#define DC    4
#define NTOK  (B_ * L_)      // 2048 tokens
#define XDBLW 96             // DT_RANK + 2*N

// ---------------------------------------------------------------------------
// Scratch (static __device__ arrays -- allocation-free per harness rules)
// ---------------------------------------------------------------------------
__device__ float  g_xz   [(size_t)NTOK * 2 * DI];
__device__ float  g_xconv[(size_t)NTOK * DI];
__device__ float  g_xdbl [(size_t)NTOK * XDBLW];
__device__ float  g_delta[(size_t)NTOK * DI];
// fp16 operands for the tensor-core GEMMs
__device__ __half g_hsH   [(size_t)NTOK * DM];      // A of GEMM1 [M,K]
__device__ __half g_WinTH [(size_t)(2 * DI) * DM];  // B^T of GEMM1 [N,K]
__device__ __half g_xdH   [(size_t)NTOK * DTR];     // A of GEMM4
__device__ __half g_WdtTH [(size_t)DI * DTR];       // B^T of GEMM4
__device__ __half g_ybH   [(size_t)NTOK * DI];      // A of GEMM6 (written by scan)
__device__ __half g_WoutTH[(size_t)DM * DI];        // B^T of GEMM6

// ---------------------------------------------------------------------------
// Helpers
// ---------------------------------------------------------------------------
__device__ __forceinline__ float silu_f(float x) {
    return x / (1.0f + __expf(-x));
}
__device__ __forceinline__ float softplus_f(float x) {
    return (x > 20.0f) ? x : log1pf(__expf(x));
}

#define CPA16(smp, gp) \
    asm volatile("cp.async.cg.shared.global [%0], [%1], 16;\n" :: "r"(smp), "l"(gp))
#define CPA_COMMIT()  asm volatile("cp.async.commit_group;\n")
#define CPA_WAIT1()   asm volatile("cp.async.wait_group 1;\n" ::: "memory")
#define CPA_WAIT0()   asm volatile("cp.async.wait_group 0;\n" ::: "memory")

__device__ __forceinline__ uint32_t smem_u32(const void* p) {
    uint32_t a;
    asm("{ .reg .u64 t; cvta.to.shared.u64 t, %1; cvt.u32.u64 %0, t; }"
        : "=r"(a) : "l"(p));
    return a;
}

__device__ __forceinline__ void mma_f16(float* c,
                                        uint32_t a0, uint32_t a1, uint32_t a2, uint32_t a3,
                                        uint32_t b0, uint32_t b1) {
    asm volatile(
        "mma.sync.aligned.m16n8k16.row.col.f32.f16.f16.f32 "
        "{%0,%1,%2,%3}, {%4,%5,%6,%7}, {%8,%9}, {%0,%1,%2,%3};\n"
        : "+f"(c[0]), "+f"(c[1]), "+f"(c[2]), "+f"(c[3])
        : "r"(a0), "r"(a1), "r"(a2), "r"(a3), "r"(b0), "r"(b1));
}

// ---------------------------------------------------------------------------
// FP16 tensor-core GEMM: C[M,N] = A[M,K] @ Bt[N,K]^T, fp32 accumulate.
// Block tile 128x128, K-tile 16, 256 threads (8 warps, warp tile 64x32).
// cp.async double-buffered.
// EPI: 0 = plain store, 1 = softplus(acc + bias[col])
// ---------------------------------------------------------------------------
template <int EPI>
__global__ void __launch_bounds__(256)
tgemm_h(const __half* __restrict__ A, const __half* __restrict__ Bt,
        float* __restrict__ C, int K, int ldc, const float* __restrict__ bias)
{
    __shared__ __align__(16) __half As[2][128][24];  // 24-half row stride: conflict-free
    __shared__ __align__(16) __half Bs[2][128][24];

    const int tid  = threadIdx.x;
    const int bm   = blockIdx.y * 128;
    const int bn   = blockIdx.x * 128;
    const int lane = tid & 31;
    const int wid  = tid >> 5;
    const int wm   = (wid & 1) * 64;
    const int wn   = (wid >> 1) * 32;
    const int g    = lane >> 2;          // 0..7
    const int t    = lane & 3;           // 0..3

    const int r   = tid >> 1;
    const int cch = tid & 1;

    const __half* Ag = A  + (size_t)(bm + r) * K + cch * 8;
    const __half* Bg = Bt + (size_t)(bn + r) * K + cch * 8;

    const uint32_t ABUFB = 128 * 24 * 2;  // bytes per buffer
    const uint32_t stA = smem_u32(&As[0][r][cch * 8]);
    const uint32_t stB = smem_u32(&Bs[0][r][cch * 8]);

#define STAGE(kt, bf)                                  \
    {                                                  \
        CPA16(stA + (bf) * ABUFB, Ag + (size_t)(kt) * 16); \
        CPA16(stB + (bf) * ABUFB, Bg + (size_t)(kt) * 16); \
        CPA_COMMIT();                                  \
    }

    float acc[4][4][4];
    #pragma unroll
    for (int mi = 0; mi < 4; mi++)
        #pragma unroll
        for (int ni = 0; ni < 4; ni++)
            #pragma unroll
            for (int q = 0; q < 4; q++) acc[mi][ni][q] = 0.0f;

    const int nIter = K / 16;
    STAGE(0, 0);

    int buf = 0;
    for (int it = 0; it < nIter; ++it) {
        if (it + 1 < nIter) {
            STAGE(it + 1, buf ^ 1);
            CPA_WAIT1();
        } else {
            CPA_WAIT0();
        }
        __syncthreads();

        uint32_t a0[4], a1[4], a2[4], a3[4], b0[4], b1[4];
        #pragma unroll
        for (int mi = 0; mi < 4; mi++) {
            const int m0 = wm + mi * 16;
            a0[mi] = *(const uint32_t*)&As[buf][m0 + g][2 * t];
            a1[mi] = *(const uint32_t*)&As[buf][m0 + g + 8][2 * t];
            a2[mi] = *(const uint32_t*)&As[buf][m0 + g][2 * t + 8];
            a3[mi] = *(const uint32_t*)&As[buf][m0 + g + 8][2 * t + 8];
        }
        #pragma unroll
        for (int ni = 0; ni < 4; ni++) {
            const int n0 = wn + ni * 8 + g;
            b0[ni] = *(const uint32_t*)&Bs[buf][n0][2 * t];
            b1[ni] = *(const uint32_t*)&Bs[buf][n0][2 * t + 8];
        }
        #pragma unroll
        for (int mi = 0; mi < 4; mi++)
            #pragma unroll
            for (int ni = 0; ni < 4; ni++)
                mma_f16(acc[mi][ni], a0[mi], a1[mi], a2[mi], a3[mi],
                        b0[ni], b1[ni]);

        buf ^= 1;
        __syncthreads();
    }

    #pragma unroll
    for (int mi = 0; mi < 4; mi++) {
        #pragma unroll
        for (int ni = 0; ni < 4; ni++) {
            const int row = bm + wm + mi * 16 + g;
            const int col = bn + wn + ni * 8 + 2 * t;
            float v0 = acc[mi][ni][0], v1 = acc[mi][ni][1];
            float v2 = acc[mi][ni][2], v3 = acc[mi][ni][3];
            if (EPI == 1) {
                const float c0 = bias[col], c1 = bias[col + 1];
                v0 = softplus_f(v0 + c0);
                v1 = softplus_f(v1 + c1);
                v2 = softplus_f(v2 + c0);
                v3 = softplus_f(v3 + c1);
            }
            *(float2*)(C + (size_t)row * ldc + col)       = make_float2(v0, v1);
            *(float2*)(C + (size_t)(row + 8) * ldc + col) = make_float2(v2, v3);
        }
    }
#undef STAGE
}

// ---------------------------------------------------------------------------
// Prep A -> half (pairs)
// ---------------------------------------------------------------------------
__global__ void prepA_h(const float* __restrict__ in, __half* __restrict__ out,
                        int MKhalf, int kbits, int ldin)
{
    int idx = blockIdx.x * blockDim.x + threadIdx.x;
    if (idx >= MKhalf) return;
    int e  = idx * 2;
    int m  = e >> kbits;
    int k  = e & ((1 << kbits) - 1);
    const float* p = in + (size_t)m * ldin + k;
    ((__half2*)out)[idx] = __floats2half2_rn(p[0], p[1]);
}

// ---------------------------------------------------------------------------
// Prep B^T -> half: out[n][k] = half(W[k][n]).  W is (K, N) row-major.
// ---------------------------------------------------------------------------
__global__ void prepBt_h(const float* __restrict__ W, __half* __restrict__ out,
                         int K, int N)
{
    __shared__ float tile[32][33];
    const int k0 = blockIdx.y * 32;
    const int n0 = blockIdx.x * 32;
    const int tx = threadIdx.x, ty = threadIdx.y;   // 32 x 8

    #pragma unroll
    for (int j = 0; j < 32; j += 8)
        tile[ty + j][tx] = W[(size_t)(k0 + ty + j) * N + n0 + tx];
    __syncthreads();

    #pragma unroll
    for (int j = 0; j < 32; j += 8)
        out[(size_t)(n0 + ty + j) * K + k0 + tx] = __float2half(tile[tx][ty + j]);
}

// ---------------------------------------------------------------------------
// Causal depthwise conv (k=4) + SiLU on the x half of xz
// ---------------------------------------------------------------------------
__global__ void conv_silu_kernel(const float* __restrict__ xz,
                                 const float* __restrict__ kw,
                                 const float* __restrict__ kb,
                                 float* __restrict__ out)
{
    int idx = blockIdx.x * blockDim.x + threadIdx.x;
    if (idx >= NTOK * DI) return;
    int d = idx & (DI - 1);
    int t = idx >> 11;
    int l = t & (L_ - 1);

    float acc = kb[d];
    #pragma unroll
    for (int i = 0; i < DC; i++) {
        int ls = l - (DC - 1) + i;
        if (ls >= 0)
            acc = fmaf(xz[(size_t)(t - (DC - 1) + i) * (2 * DI) + d],
                       kw[i * DI + d], acc);
    }
    out[idx] = silu_f(acc);
}

// ---------------------------------------------------------------------------
// x_dbl = xconv @ Wx   (NTOK x 96, K=2048). 4 token rows per block.
// ---------------------------------------------------------------------------
#define XR 4
__global__ void __launch_bounds__(96)
xdbl_kernel(const float* __restrict__ xc, const float* __restrict__ Wx,
            float* __restrict__ out)
{
    __shared__ float sh[XR][DI];
    const int row0 = blockIdx.x * XR;
    const int col  = threadIdx.x;
    for (int i = col; i < XR * DI; i += 96)
        ((float*)sh)[i] = xc[(size_t)row0 * DI + i];
    __syncthreads();

    float acc[XR] = {0.0f, 0.0f, 0.0f, 0.0f};
    for (int k = 0; k < DI; k++) {
        float w = Wx[(size_t)k * XDBLW + col];
        #pragma unroll
        for (int r = 0; r < XR; r++)
            acc[r] = fmaf(sh[r][k], w, acc[r]);
    }
    #pragma unroll
    for (int r = 0; r < XR; r++)
        out[(size_t)(row0 + r) * XDBLW + col] = acc[r];
}

// ---------------------------------------------------------------------------
// Selective scan, deep-prefetch (PF=8 tokens of loads in flight).
// One thread per (channel, state-n); 16-lane groups reduce y over n.
// Writes gated output DIRECTLY as fp16 (A operand of the out-proj GEMM).
// ---------------------------------------------------------------------------
#define PF 8
__global__ void __launch_bounds__(256)
scan_kernel(const float* __restrict__ delta, const float* __restrict__ u,
            const float* __restrict__ xdbl,  const float* __restrict__ xz,
            const float* __restrict__ A_log, const float* __restrict__ Dskip,
            __half* __restrict__ yH)
{
    const int tid = threadIdx.x;
    const int grp = tid >> 4;
    const int n   = tid & 15;
    const int c   = blockIdx.x * 16 + grp;
    const int b   = c >> 11;
    const int d   = c & (DI - 1);

    const float An = -__expf(A_log[d * NS + n]);
    const float Dd = Dskip[d];

    const float* drow = delta + (size_t)b * L_ * DI + d;
    const float* urow = u     + (size_t)b * L_ * DI + d;
    const float* zrow = xz    + (size_t)b * L_ * (2 * DI) + DI + d;
    const float* brow = xdbl  + (size_t)b * L_ * XDBLW + DTR + n;
    __half*      yrow = yH    + (size_t)b * L_ * DI + d;

    float pdv[PF], puv[PF], pBn[PF], pCn[PF];
    #pragma unroll
    for (int i = 0; i < PF; i++) {
        pdv[i] = drow[(size_t)i * DI];
        puv[i] = urow[(size_t)i * DI];
        pBn[i] = brow[(size_t)i * XDBLW];
        pCn[i] = brow[(size_t)i * XDBLW + NS];
    }

    float x = 0.0f;
    for (int l = 0; l < L_; l += PF) {
        #pragma unroll
        for (int i = 0; i < PF; i++) {
            const float dv = pdv[i], uv = puv[i], Bn = pBn[i], Cn = pCn[i];
            const int ln = l + i + PF;
            if (ln < L_) {
                pdv[i] = drow[(size_t)ln * DI];
                puv[i] = urow[(size_t)ln * DI];
                pBn[i] = brow[(size_t)ln * XDBLW];
                pCn[i] = brow[(size_t)ln * XDBLW + NS];
            }
            float dA = __expf(dv * An);
            x = fmaf(dA, x, dv * Bn * uv);
            float v = x * Cn;
            v += __shfl_xor_sync(0xffffffffu, v, 1, 16);
            v += __shfl_xor_sync(0xffffffffu, v, 2, 16);
            v += __shfl_xor_sync(0xffffffffu, v, 4, 16);
            v += __shfl_xor_sync(0xffffffffu, v, 8, 16);
            if (n == 0) {
                float zv = zrow[(size_t)(l + i) * (2 * DI)];
                yrow[(size_t)(l + i) * DI] =
                    __float2half((v + uv * Dd) * silu_f(zv));
            }
        }
    }
}

// ---------------------------------------------------------------------------
// Launch
// ---------------------------------------------------------------------------
extern "C" void kernel_launch(void* const* d_in, const int* in_sizes, int n_in,
                              void* d_out, int out_size)
{
    const float* hs      = (const float*)d_in[0];
    const float* Win     = (const float*)d_in[1];
    const float* Wx      = (const float*)d_in[2];
    const float* Wdt     = (const float*)d_in[3];
    const float* dt_bias = (const float*)d_in[4];
    const float* Wout    = (const float*)d_in[5];
    const float* dwk     = (const float*)d_in[6];
    const float* dwb     = (const float*)d_in[7];
    const float* A_log   = (const float*)d_in[8];
    const float* Dskip   = (const float*)d_in[9];
    float* out = (float*)d_out;

    float  *xz, *xc, *xd, *dl;
    __half *hsH, *WinTH, *xdH, *WdtTH, *ybH, *WoutTH;
    cudaGetSymbolAddress((void**)&xz,     g_xz);
    cudaGetSymbolAddress((void**)&xc,     g_xconv);
    cudaGetSymbolAddress((void**)&xd,     g_xdbl);
    cudaGetSymbolAddress((void**)&dl,     g_delta);
    cudaGetSymbolAddress((void**)&hsH,    g_hsH);
    cudaGetSymbolAddress((void**)&WinTH,  g_WinTH);
    cudaGetSymbolAddress((void**)&xdH,    g_xdH);
    cudaGetSymbolAddress((void**)&WdtTH,  g_WdtTH);
    cudaGetSymbolAddress((void**)&ybH,    g_ybH);
    cudaGetSymbolAddress((void**)&WoutTH, g_WoutTH);

    // --- prep fp16 operands available up-front ---
    prepA_h<<<(NTOK * DM / 2) / 256, 256>>>(hs, hsH, NTOK * DM / 2, 10, DM);
    prepBt_h<<<dim3((2 * DI) / 32, DM / 32), dim3(32, 8)>>>(Win, WinTH, DM, 2 * DI);
    prepBt_h<<<dim3(DI / 32, DTR / 32), dim3(32, 8)>>>(Wdt, WdtTH, DTR, DI);
    prepBt_h<<<dim3(DM / 32, DI / 32), dim3(32, 8)>>>(Wout, WoutTH, DI, DM);

    // 1) xz = hidden @ Win            (2048 x 4096, K=1024)
    tgemm_h<0><<<dim3(4096 / 128, 2048 / 128), 256>>>(
        hsH, WinTH, xz, DM, 2 * DI, nullptr);

    // 2) depthwise causal conv + silu on x half
    conv_silu_kernel<<<(NTOK * DI + 255) / 256, 256>>>(xz, dwk, dwb, xc);

    // 3) x_dbl = xconv @ Wx           (2048 x 96, K=2048)
    xdbl_kernel<<<NTOK / XR, 96>>>(xc, Wx, xd);

    // 4) delta = softplus(dt @ Wdt + dt_bias)   (2048 x 2048, K=64)
    prepA_h<<<(NTOK * DTR / 2) / 256, 256>>>(xd, xdH, NTOK * DTR / 2, 6, XDBLW);
    tgemm_h<1><<<dim3(2048 / 128, 2048 / 128), 256>>>(
        xdH, WdtTH, dl, DTR, DI, dt_bias);

    // 5) selective scan (+skip, *silu(z)) -> fp16 directly
    scan_kernel<<<(B_ * DI) / 16, 256>>>(dl, xc, xd, xz, A_log, Dskip, ybH);

    // 6) out = y @ Wout               (2048 x 1024, K=2048)
    tgemm_h<0><<<dim3(1024 / 128, 2048 / 128), 256>>>(
        ybH, WoutTH, out, DI, DM, nullptr);
}

// round 11
// speedup vs baseline: 1.4871x; 1.0018x over previous
#include <cuda_runtime.h>
#include <cuda_fp16.h>
#include <math.h>
#include <stdint.h>

// Problem dims (fixed by the dataset)
#define B_    2
#define L_    1024
#define DM    1024
#define DI    2048
#define NS    16
#define DTR   64
#define DC    4
#define NTOK  (B_ * L_)      // 2048 tokens
#define XDBLW 96             // DT_RANK + 2*N

// ---------------------------------------------------------------------------
// Scratch (static __device__ arrays -- allocation-free per harness rules)
// ---------------------------------------------------------------------------
__device__ float  g_xz   [(size_t)NTOK * 2 * DI];
__device__ float  g_xconv[(size_t)NTOK * DI];
__device__ float  g_xdbl [(size_t)NTOK * XDBLW];
__device__ float  g_delta[(size_t)NTOK * DI];
// fp16 operands for the tensor-core GEMMs
__device__ __half g_hsH   [(size_t)NTOK * DM];      // A of GEMM1 [M,K]
__device__ __half g_WinTH [(size_t)(2 * DI) * DM];  // B^T of GEMM1 [N,K]
__device__ __half g_xdH   [(size_t)NTOK * DTR];     // A of GEMM4
__device__ __half g_WdtTH [(size_t)DI * DTR];       // B^T of GEMM4
__device__ __half g_ybH   [(size_t)NTOK * DI];      // A of GEMM6 (written by scan)
__device__ __half g_WoutTH[(size_t)DM * DI];        // B^T of GEMM6

// ---------------------------------------------------------------------------
// Helpers
// ---------------------------------------------------------------------------
__device__ __forceinline__ float silu_f(float x) {
    return x / (1.0f + __expf(-x));
}
__device__ __forceinline__ float softplus_f(float x) {
    return (x > 20.0f) ? x : log1pf(__expf(x));
}

#define CPA16(smp, gp) \
    asm volatile("cp.async.cg.shared.global [%0], [%1], 16;\n" :: "r"(smp), "l"(gp))
#define CPA_COMMIT()  asm volatile("cp.async.commit_group;\n")
#define CPA_WAIT1()   asm volatile("cp.async.wait_group 1;\n" ::: "memory")
#define CPA_WAIT0()   asm volatile("cp.async.wait_group 0;\n" ::: "memory")

__device__ __forceinline__ uint32_t smem_u32(const void* p) {
    uint32_t a;
    asm("{ .reg .u64 t; cvta.to.shared.u64 t, %1; cvt.u32.u64 %0, t; }"
        : "=r"(a) : "l"(p));
    return a;
}

__device__ __forceinline__ void mma_f16(float* c,
                                        uint32_t a0, uint32_t a1, uint32_t a2, uint32_t a3,
                                        uint32_t b0, uint32_t b1) {
    asm volatile(
        "mma.sync.aligned.m16n8k16.row.col.f32.f16.f16.f32 "
        "{%0,%1,%2,%3}, {%4,%5,%6,%7}, {%8,%9}, {%0,%1,%2,%3};\n"
        : "+f"(c[0]), "+f"(c[1]), "+f"(c[2]), "+f"(c[3])
        : "r"(a0), "r"(a1), "r"(a2), "r"(a3), "r"(b0), "r"(b1));
}

#define LDSM_X4(r0, r1, r2, r3, addr)                                        \
    asm volatile("ldmatrix.sync.aligned.m8n8.x4.shared.b16 {%0,%1,%2,%3}, [%4];" \
                 : "=r"(r0), "=r"(r1), "=r"(r2), "=r"(r3) : "r"(addr))

// ---------------------------------------------------------------------------
// FP16 tensor-core GEMM: C[M,N] = A[M,K] @ Bt[N,K]^T, fp32 accumulate.
// Block tile 128x128, BK=32, 256 threads (8 warps, warp tile 64x32).
// Fragments via ldmatrix.x4 (12 per warp per K32-iter); cp.async dbl-buffer.
// Requires K multiple of 32.
// EPI: 0 = plain store, 1 = softplus(acc + bias[col])
// ---------------------------------------------------------------------------
#define ROWH 40   // 32 k-halves + 8 pad -> 80B row stride, LDSM conflict-free

template <int EPI>
__global__ void __launch_bounds__(256)
tgemm_h(const __half* __restrict__ A, const __half* __restrict__ Bt,
        float* __restrict__ C, int K, int ldc, const float* __restrict__ bias)
{
    __shared__ __align__(16) __half As[2][128][ROWH];
    __shared__ __align__(16) __half Bs[2][128][ROWH];

    const int tid  = threadIdx.x;
    const int bm   = blockIdx.y * 128;
    const int bn   = blockIdx.x * 128;
    const int lane = tid & 31;
    const int wid  = tid >> 5;
    const int wm   = (wid & 1) * 64;
    const int wn   = (wid >> 1) * 32;
    const int g    = lane >> 2;          // 0..7
    const int t    = lane & 3;           // 0..3

    // staging: A/B tiles are 128 rows x 64B; 512 16B-chunks each, 2 per thread
    const int sr = tid >> 2;             // rows sr and sr+64
    const int sc = (tid & 3) * 8;        // k-half offset (8 halves = 16B)

    const __half* Ag0 = A  + (size_t)(bm + sr) * K + sc;
    const __half* Ag1 = A  + (size_t)(bm + sr + 64) * K + sc;
    const __half* Bg0 = Bt + (size_t)(bn + sr) * K + sc;
    const __half* Bg1 = Bt + (size_t)(bn + sr + 64) * K + sc;

    const uint32_t BUFB = 128 * ROWH * 2;           // bytes per buffer
    const uint32_t R64  = 64 * ROWH * 2;            // +64 rows in bytes
    const uint32_t stA  = smem_u32(&As[0][sr][sc]);
    const uint32_t stB  = smem_u32(&Bs[0][sr][sc]);

#define STAGE(kt, bf)                                       \
    {                                                       \
        CPA16(stA + (bf) * BUFB,       Ag0 + (size_t)(kt) * 32); \
        CPA16(stA + (bf) * BUFB + R64, Ag1 + (size_t)(kt) * 32); \
        CPA16(stB + (bf) * BUFB,       Bg0 + (size_t)(kt) * 32); \
        CPA16(stB + (bf) * BUFB + R64, Bg1 + (size_t)(kt) * 32); \
        CPA_COMMIT();                                       \
    }

    // ldmatrix lane-address bases
    const int li = lane & 7;
    const int q  = lane >> 3;
    // A: reg j <- matrix j: q0:(row li, k0) q1:(row+8, k0) q2:(row li, k8) q3:(row+8, k8)
    const uint32_t aBase = smem_u32(&As[0][0][0])
        + (uint32_t)(((wm + li + 8 * (q & 1)) * ROWH + 8 * (q >> 1)) * 2);
    // B: q0:(row li, k0) q1:(row li, k8) q2:(row+8, k0) q3:(row+8, k8)
    const uint32_t bBase = smem_u32(&Bs[0][0][0])
        + (uint32_t)(((wn + li + 8 * (q >> 1)) * ROWH + 8 * (q & 1)) * 2);

    float acc[4][4][4];
    #pragma unroll
    for (int mi = 0; mi < 4; mi++)
        #pragma unroll
        for (int ni = 0; ni < 4; ni++)
            #pragma unroll
            for (int p = 0; p < 4; p++) acc[mi][ni][p] = 0.0f;

    const int nIter = K / 32;
    STAGE(0, 0);

    int buf = 0;
    for (int it = 0; it < nIter; ++it) {
        if (it + 1 < nIter) {
            STAGE(it + 1, buf ^ 1);
            CPA_WAIT1();
        } else {
            CPA_WAIT0();
        }
        __syncthreads();

        const uint32_t ab = aBase + buf * BUFB;
        const uint32_t bb_ = bBase + buf * BUFB;

        #pragma unroll
        for (int s = 0; s < 2; s++) {
            uint32_t a[4][4], bv[2][4];
            #pragma unroll
            for (int mi = 0; mi < 4; mi++)
                LDSM_X4(a[mi][0], a[mi][1], a[mi][2], a[mi][3],
                        ab + (uint32_t)((mi * 16 * ROWH + s * 16) * 2));
            #pragma unroll
            for (int p = 0; p < 2; p++)
                LDSM_X4(bv[p][0], bv[p][1], bv[p][2], bv[p][3],
                        bb_ + (uint32_t)((p * 16 * ROWH + s * 16) * 2));
            #pragma unroll
            for (int mi = 0; mi < 4; mi++)
                #pragma unroll
                for (int ni = 0; ni < 4; ni++) {
                    const int p = ni >> 1, o = (ni & 1) * 2;
                    mma_f16(acc[mi][ni], a[mi][0], a[mi][1], a[mi][2], a[mi][3],
                            bv[p][o], bv[p][o + 1]);
                }
        }

        buf ^= 1;
        __syncthreads();
    }

    #pragma unroll
    for (int mi = 0; mi < 4; mi++) {
        #pragma unroll
        for (int ni = 0; ni < 4; ni++) {
            const int row = bm + wm + mi * 16 + g;
            const int col = bn + wn + ni * 8 + 2 * t;
            float v0 = acc[mi][ni][0], v1 = acc[mi][ni][1];
            float v2 = acc[mi][ni][2], v3 = acc[mi][ni][3];
            if (EPI == 1) {
                const float c0 = bias[col], c1 = bias[col + 1];
                v0 = softplus_f(v0 + c0);
                v1 = softplus_f(v1 + c1);
                v2 = softplus_f(v2 + c0);
                v3 = softplus_f(v3 + c1);
            }
            *(float2*)(C + (size_t)row * ldc + col)       = make_float2(v0, v1);
            *(float2*)(C + (size_t)(row + 8) * ldc + col) = make_float2(v2, v3);
        }
    }
#undef STAGE
}

// ---------------------------------------------------------------------------
// Prep A -> half (pairs)
// ---------------------------------------------------------------------------
__global__ void prepA_h(const float* __restrict__ in, __half* __restrict__ out,
                        int MKhalf, int kbits, int ldin)
{
    int idx = blockIdx.x * blockDim.x + threadIdx.x;
    if (idx >= MKhalf) return;
    int e  = idx * 2;
    int m  = e >> kbits;
    int k  = e & ((1 << kbits) - 1);
    const float* p = in + (size_t)m * ldin + k;
    ((__half2*)out)[idx] = __floats2half2_rn(p[0], p[1]);
}

// ---------------------------------------------------------------------------
// Prep B^T -> half: out[n][k] = half(W[k][n]).  W is (K, N) row-major.
// ---------------------------------------------------------------------------
__global__ void prepBt_h(const float* __restrict__ W, __half* __restrict__ out,
                         int K, int N)
{
    __shared__ float tile[32][33];
    const int k0 = blockIdx.y * 32;
    const int n0 = blockIdx.x * 32;
    const int tx = threadIdx.x, ty = threadIdx.y;   // 32 x 8

    #pragma unroll
    for (int j = 0; j < 32; j += 8)
        tile[ty + j][tx] = W[(size_t)(k0 + ty + j) * N + n0 + tx];
    __syncthreads();

    #pragma unroll
    for (int j = 0; j < 32; j += 8)
        out[(size_t)(n0 + ty + j) * K + k0 + tx] = __float2half(tile[tx][ty + j]);
}

// ---------------------------------------------------------------------------
// Causal depthwise conv (k=4) + SiLU on the x half of xz
// ---------------------------------------------------------------------------
__global__ void conv_silu_kernel(const float* __restrict__ xz,
                                 const float* __restrict__ kw,
                                 const float* __restrict__ kb,
                                 float* __restrict__ out)
{
    int idx = blockIdx.x * blockDim.x + threadIdx.x;
    if (idx >= NTOK * DI) return;
    int d = idx & (DI - 1);
    int t = idx >> 11;
    int l = t & (L_ - 1);

    float acc = kb[d];
    #pragma unroll
    for (int i = 0; i < DC; i++) {
        int ls = l - (DC - 1) + i;
        if (ls >= 0)
            acc = fmaf(xz[(size_t)(t - (DC - 1) + i) * (2 * DI) + d],
                       kw[i * DI + d], acc);
    }
    out[idx] = silu_f(acc);
}

// ---------------------------------------------------------------------------
// x_dbl = xconv @ Wx   (NTOK x 96, K=2048). 4 token rows per block.
// ---------------------------------------------------------------------------
#define XR 4
__global__ void __launch_bounds__(96)
xdbl_kernel(const float* __restrict__ xc, const float* __restrict__ Wx,
            float* __restrict__ out)
{
    __shared__ float sh[XR][DI];
    const int row0 = blockIdx.x * XR;
    const int col  = threadIdx.x;
    for (int i = col; i < XR * DI; i += 96)
        ((float*)sh)[i] = xc[(size_t)row0 * DI + i];
    __syncthreads();

    float acc[XR] = {0.0f, 0.0f, 0.0f, 0.0f};
    for (int k = 0; k < DI; k++) {
        float w = Wx[(size_t)k * XDBLW + col];
        #pragma unroll
        for (int r = 0; r < XR; r++)
            acc[r] = fmaf(sh[r][k], w, acc[r]);
    }
    #pragma unroll
    for (int r = 0; r < XR; r++)
        out[(size_t)(row0 + r) * XDBLW + col] = acc[r];
}

// ---------------------------------------------------------------------------
// Selective scan, deep-prefetch (PF=8 tokens of loads in flight).
// One thread per (channel, state-n); 16-lane groups reduce y over n.
// Writes gated output DIRECTLY as fp16 (A operand of the out-proj GEMM).
// ---------------------------------------------------------------------------
#define PF 8
__global__ void __launch_bounds__(256)
scan_kernel(const float* __restrict__ delta, const float* __restrict__ u,
            const float* __restrict__ xdbl,  const float* __restrict__ xz,
            const float* __restrict__ A_log, const float* __restrict__ Dskip,
            __half* __restrict__ yH)
{
    const int tid = threadIdx.x;
    const int grp = tid >> 4;
    const int n   = tid & 15;
    const int c   = blockIdx.x * 16 + grp;
    const int b   = c >> 11;
    const int d   = c & (DI - 1);

    const float An = -__expf(A_log[d * NS + n]);
    const float Dd = Dskip[d];

    const float* drow = delta + (size_t)b * L_ * DI + d;
    const float* urow = u     + (size_t)b * L_ * DI + d;
    const float* zrow = xz    + (size_t)b * L_ * (2 * DI) + DI + d;
    const float* brow = xdbl  + (size_t)b * L_ * XDBLW + DTR + n;
    __half*      yrow = yH    + (size_t)b * L_ * DI + d;

    float pdv[PF], puv[PF], pBn[PF], pCn[PF];
    #pragma unroll
    for (int i = 0; i < PF; i++) {
        pdv[i] = drow[(size_t)i * DI];
        puv[i] = urow[(size_t)i * DI];
        pBn[i] = brow[(size_t)i * XDBLW];
        pCn[i] = brow[(size_t)i * XDBLW + NS];
    }

    float x = 0.0f;
    for (int l = 0; l < L_; l += PF) {
        #pragma unroll
        for (int i = 0; i < PF; i++) {
            const float dv = pdv[i], uv = puv[i], Bn = pBn[i], Cn = pCn[i];
            const int ln = l + i + PF;
            if (ln < L_) {
                pdv[i] = drow[(size_t)ln * DI];
                puv[i] = urow[(size_t)ln * DI];
                pBn[i] = brow[(size_t)ln * XDBLW];
                pCn[i] = brow[(size_t)ln * XDBLW + NS];
            }
            float dA = __expf(dv * An);
            x = fmaf(dA, x, dv * Bn * uv);
            float v = x * Cn;
            v += __shfl_xor_sync(0xffffffffu, v, 1, 16);
            v += __shfl_xor_sync(0xffffffffu, v, 2, 16);
            v += __shfl_xor_sync(0xffffffffu, v, 4, 16);
            v += __shfl_xor_sync(0xffffffffu, v, 8, 16);
            if (n == 0) {
                float zv = zrow[(size_t)(l + i) * (2 * DI)];
                yrow[(size_t)(l + i) * DI] =
                    __float2half((v + uv * Dd) * silu_f(zv));
            }
        }
    }
}

// ---------------------------------------------------------------------------
// Launch.  Order chosen so the big GEMM is launch #4 (the one ncu captures).
// ---------------------------------------------------------------------------
extern "C" void kernel_launch(void* const* d_in, const int* in_sizes, int n_in,
                              void* d_out, int out_size)
{
    const float* hs      = (const float*)d_in[0];
    const float* Win     = (const float*)d_in[1];
    const float* Wx      = (const float*)d_in[2];
    const float* Wdt     = (const float*)d_in[3];
    const float* dt_bias = (const float*)d_in[4];
    const float* Wout    = (const float*)d_in[5];
    const float* dwk     = (const float*)d_in[6];
    const float* dwb     = (const float*)d_in[7];
    const float* A_log   = (const float*)d_in[8];
    const float* Dskip   = (const float*)d_in[9];
    float* out = (float*)d_out;

    float  *xz, *xc, *xd, *dl;
    __half *hsH, *WinTH, *xdH, *WdtTH, *ybH, *WoutTH;
    cudaGetSymbolAddress((void**)&xz,     g_xz);
    cudaGetSymbolAddress((void**)&xc,     g_xconv);
    cudaGetSymbolAddress((void**)&xd,     g_xdbl);
    cudaGetSymbolAddress((void**)&dl,     g_delta);
    cudaGetSymbolAddress((void**)&hsH,    g_hsH);
    cudaGetSymbolAddress((void**)&WinTH,  g_WinTH);
    cudaGetSymbolAddress((void**)&xdH,    g_xdH);
    cudaGetSymbolAddress((void**)&WdtTH,  g_WdtTH);
    cudaGetSymbolAddress((void**)&ybH,    g_ybH);
    cudaGetSymbolAddress((void**)&WoutTH, g_WoutTH);

    // #1-#3: preps needed for GEMM1 (+ Wdt while we're at it)
    prepA_h<<<(NTOK * DM / 2) / 256, 256>>>(hs, hsH, NTOK * DM / 2, 10, DM);
    prepBt_h<<<dim3((2 * DI) / 32, DM / 32), dim3(32, 8)>>>(Win, WinTH, DM, 2 * DI);
    prepBt_h<<<dim3(DI / 32, DTR / 32), dim3(32, 8)>>>(Wdt, WdtTH, DTR, DI);

    // #4: xz = hidden @ Win            (2048 x 4096, K=1024)  <- profiled slot
    tgemm_h<0><<<dim3(4096 / 128, 2048 / 128), 256>>>(
        hsH, WinTH, xz, DM, 2 * DI, nullptr);

    // #5: depthwise causal conv + silu on x half
    conv_silu_kernel<<<(NTOK * DI + 255) / 256, 256>>>(xz, dwk, dwb, xc);

    // #6: x_dbl = xconv @ Wx           (2048 x 96, K=2048)
    xdbl_kernel<<<NTOK / XR, 96>>>(xc, Wx, xd);

    // #7-#8: delta = softplus(dt @ Wdt + dt_bias)   (2048 x 2048, K=64)
    prepA_h<<<(NTOK * DTR / 2) / 256, 256>>>(xd, xdH, NTOK * DTR / 2, 6, XDBLW);
    tgemm_h<1><<<dim3(2048 / 128, 2048 / 128), 256>>>(
        xdH, WdtTH, dl, DTR, DI, dt_bias);

    // #9: prep Wout (needed before GEMM6)
    prepBt_h<<<dim3(DM / 32, DI / 32), dim3(32, 8)>>>(Wout, WoutTH, DI, DM);

    // #10: selective scan (+skip, *silu(z)) -> fp16 directly
    scan_kernel<<<(B_ * DI) / 16, 256>>>(dl, xc, xd, xz, A_log, Dskip, ybH);

    // #11: out = y @ Wout              (2048 x 1024, K=2048)
    tgemm_h<0><<<dim3(1024 / 128, 2048 / 128), 256>>>(
        ybH, WoutTH, out, DI, DM, nullptr);
}

// round 12
// speedup vs baseline: 1.5762x; 1.0599x over previous
#include <cuda_runtime.h>
#include <cuda_fp16.h>
#include <math.h>
#include <stdint.h>

// Problem dims (fixed by the dataset)
#define B_    2
#define L_    1024
#define DM    1024
#define DI    2048
#define NS    16
#define DTR   64
#define DC    4
#define NTOK  (B_ * L_)      // 2048 tokens
#define XDBLW 96             // DT_RANK + 2*N

// ---------------------------------------------------------------------------
// Scratch (static __device__ arrays -- allocation-free per harness rules)
// ---------------------------------------------------------------------------
__device__ float  g_xz   [(size_t)NTOK * 2 * DI];
__device__ float  g_xconv[(size_t)NTOK * DI];
__device__ float  g_xdbl [(size_t)NTOK * XDBLW];
__device__ float  g_delta[(size_t)NTOK * DI];
// fp16 operands for the tensor-core GEMMs
__device__ __half g_hsH   [(size_t)NTOK * DM];
__device__ __half g_WinTH [(size_t)(2 * DI) * DM];
__device__ __half g_xdH   [(size_t)NTOK * DTR];
__device__ __half g_WdtTH [(size_t)DI * DTR];
__device__ __half g_ybH   [(size_t)NTOK * DI];
__device__ __half g_WoutTH[(size_t)DM * DI];

// ---------------------------------------------------------------------------
// Helpers
// ---------------------------------------------------------------------------
__device__ __forceinline__ float silu_f(float x) {
    return x / (1.0f + __expf(-x));
}
__device__ __forceinline__ float softplus_f(float x) {
    return (x > 20.0f) ? x : log1pf(__expf(x));
}

#define CPA16(smp, gp) \
    asm volatile("cp.async.cg.shared.global [%0], [%1], 16;\n" :: "r"(smp), "l"(gp))
#define CPA_COMMIT()  asm volatile("cp.async.commit_group;\n")
#define CPA_WAIT1()   asm volatile("cp.async.wait_group 1;\n" ::: "memory")
#define CPA_WAIT0()   asm volatile("cp.async.wait_group 0;\n" ::: "memory")

__device__ __forceinline__ uint32_t smem_u32(const void* p) {
    uint32_t a;
    asm("{ .reg .u64 t; cvta.to.shared.u64 t, %1; cvt.u32.u64 %0, t; }"
        : "=r"(a) : "l"(p));
    return a;
}

__device__ __forceinline__ void mma_f16(float* c,
                                        uint32_t a0, uint32_t a1, uint32_t a2, uint32_t a3,
                                        uint32_t b0, uint32_t b1) {
    asm volatile(
        "mma.sync.aligned.m16n8k16.row.col.f32.f16.f16.f32 "
        "{%0,%1,%2,%3}, {%4,%5,%6,%7}, {%8,%9}, {%0,%1,%2,%3};\n"
        : "+f"(c[0]), "+f"(c[1]), "+f"(c[2]), "+f"(c[3])
        : "r"(a0), "r"(a1), "r"(a2), "r"(a3), "r"(b0), "r"(b1));
}

#define LDSM_X4(r0, r1, r2, r3, addr)                                        \
    asm volatile("ldmatrix.sync.aligned.m8n8.x4.shared.b16 {%0,%1,%2,%3}, [%4];" \
                 : "=r"(r0), "=r"(r1), "=r"(r2), "=r"(r3) : "r"(addr))

// ---------------------------------------------------------------------------
// FP16 tensor-core GEMM: C[M,N] = A[M,K] @ Bt[N,K]^T, fp32 accumulate.
// Block tile 128xBN (BN=128 or 64), BK=32, 256 threads.
// 3-stage cp.async pipeline, ONE __syncthreads per K-iter.
// ldmatrix.x4 fragments; dynamic smem.  Requires K multiple of 32.
// EPI: 0 = plain store, 1 = softplus(acc + bias[col])
// ---------------------------------------------------------------------------
#define ROWH 40   // 80B row stride: 16B-aligned, LDSM conflict-free
#define NSTG 3

template <int EPI, int BN>
__global__ void __launch_bounds__(256)
tgemm_h(const __half* __restrict__ A, const __half* __restrict__ Bt,
        float* __restrict__ C, int K, int ldc, const float* __restrict__ bias)
{
    constexpr int MI   = (BN == 128) ? 4 : 2;       // 16-row frags per warp
    constexpr uint32_t ASTG = 128 * ROWH * 2;       // bytes per A stage
    constexpr uint32_t BSTG = (uint32_t)BN * ROWH * 2;

    extern __shared__ __align__(16) char dsm[];
    const uint32_t sA0 = smem_u32(dsm);             // A stages [0, 3*ASTG)
    const uint32_t sB0 = sA0 + NSTG * ASTG;         // B stages

    const int tid  = threadIdx.x;
    const int bm   = blockIdx.y * 128;
    const int bn   = blockIdx.x * BN;
    const int lane = tid & 31;
    const int wid  = tid >> 5;
    const int wm   = (BN == 128) ? (wid & 1) * 64 : (wid & 3) * 32;
    const int wn   = (BN == 128) ? (wid >> 1) * 32 : (wid >> 2) * 32;
    const int g    = lane >> 2;
    const int t    = lane & 3;

    // staging: rows sr (and sr+64 for 128-row tiles), 16B chunk sc
    const int sr = tid >> 2;             // 0..63
    const int sc = (tid & 3) * 8;        // k-half offset

    const __half* Ag0 = A + (size_t)(bm + sr) * K + sc;
    const __half* Ag1 = A + (size_t)(bm + sr + 64) * K + sc;
    const __half* Bg0 = Bt + (size_t)(bn + sr) * K + sc;
    const __half* Bg1 = (BN == 128) ? Bt + (size_t)(bn + sr + 64) * K + sc : Bg0;

    const uint32_t R64  = 64 * ROWH * 2;
    const uint32_t stA  = sA0 + (uint32_t)(sr * ROWH + sc) * 2;
    const uint32_t stB  = sB0 + (uint32_t)(sr * ROWH + sc) * 2;

#define STAGE(kt, bf)                                             \
    {                                                             \
        CPA16(stA + (bf) * ASTG,       Ag0 + (size_t)(kt) * 32);  \
        CPA16(stA + (bf) * ASTG + R64, Ag1 + (size_t)(kt) * 32);  \
        CPA16(stB + (bf) * BSTG,       Bg0 + (size_t)(kt) * 32);  \
        if (BN == 128)                                            \
            CPA16(stB + (bf) * BSTG + R64, Bg1 + (size_t)(kt) * 32); \
        CPA_COMMIT();                                             \
    }

    // ldmatrix lane-address bases
    const int li = lane & 7;
    const int q  = lane >> 3;
    const uint32_t aBase = sA0
        + (uint32_t)(((wm + li + 8 * (q & 1)) * ROWH + 8 * (q >> 1)) * 2);
    const uint32_t bBase = sB0
        + (uint32_t)(((wn + li + 8 * (q >> 1)) * ROWH + 8 * (q & 1)) * 2);

    float acc[MI][4][4];
    #pragma unroll
    for (int mi = 0; mi < MI; mi++)
        #pragma unroll
        for (int ni = 0; ni < 4; ni++)
            #pragma unroll
            for (int p = 0; p < 4; p++) acc[mi][ni][p] = 0.0f;

    const int nIter = K / 32;

    STAGE(0, 0);
    STAGE(1, 1);

    int buf = 0;
    for (int it = 0; it < nIter; ++it) {
        if (it < nIter - 1) { CPA_WAIT1(); } else { CPA_WAIT0(); }
        __syncthreads();
        if (it + 2 < nIter) {
            int nb = buf + 2; if (nb >= NSTG) nb -= NSTG;
            STAGE(it + 2, nb);
        }

        const uint32_t ab  = aBase + buf * ASTG;
        const uint32_t bb_ = bBase + buf * BSTG;

        #pragma unroll
        for (int s = 0; s < 2; s++) {
            uint32_t a[MI][4], bv[2][4];
            #pragma unroll
            for (int mi = 0; mi < MI; mi++)
                LDSM_X4(a[mi][0], a[mi][1], a[mi][2], a[mi][3],
                        ab + (uint32_t)((mi * 16 * ROWH + s * 16) * 2));
            #pragma unroll
            for (int p = 0; p < 2; p++)
                LDSM_X4(bv[p][0], bv[p][1], bv[p][2], bv[p][3],
                        bb_ + (uint32_t)((p * 16 * ROWH + s * 16) * 2));
            #pragma unroll
            for (int mi = 0; mi < MI; mi++)
                #pragma unroll
                for (int ni = 0; ni < 4; ni++) {
                    const int p = ni >> 1, o = (ni & 1) * 2;
                    mma_f16(acc[mi][ni], a[mi][0], a[mi][1], a[mi][2], a[mi][3],
                            bv[p][o], bv[p][o + 1]);
                }
        }

        if (++buf == NSTG) buf = 0;
    }

    #pragma unroll
    for (int mi = 0; mi < MI; mi++) {
        #pragma unroll
        for (int ni = 0; ni < 4; ni++) {
            const int row = bm + wm + mi * 16 + g;
            const int col = bn + wn + ni * 8 + 2 * t;
            float v0 = acc[mi][ni][0], v1 = acc[mi][ni][1];
            float v2 = acc[mi][ni][2], v3 = acc[mi][ni][3];
            if (EPI == 1) {
                const float c0 = bias[col], c1 = bias[col + 1];
                v0 = softplus_f(v0 + c0);
                v1 = softplus_f(v1 + c1);
                v2 = softplus_f(v2 + c0);
                v3 = softplus_f(v3 + c1);
            }
            *(float2*)(C + (size_t)row * ldc + col)       = make_float2(v0, v1);
            *(float2*)(C + (size_t)(row + 8) * ldc + col) = make_float2(v2, v3);
        }
    }
#undef STAGE
}

#define SMEM_G128 (NSTG * (128 + 128) * ROWH * 2)   // 61440
#define SMEM_G64  (NSTG * (128 + 64) * ROWH * 2)    // 46080

// ---------------------------------------------------------------------------
// Prep A -> half (pairs)
// ---------------------------------------------------------------------------
__global__ void prepA_h(const float* __restrict__ in, __half* __restrict__ out,
                        int MKhalf, int kbits, int ldin)
{
    int idx = blockIdx.x * blockDim.x + threadIdx.x;
    if (idx >= MKhalf) return;
    int e  = idx * 2;
    int m  = e >> kbits;
    int k  = e & ((1 << kbits) - 1);
    const float* p = in + (size_t)m * ldin + k;
    ((__half2*)out)[idx] = __floats2half2_rn(p[0], p[1]);
}

// ---------------------------------------------------------------------------
// Prep B^T -> half: out[n][k] = half(W[k][n]).  W is (K, N) row-major.
// ---------------------------------------------------------------------------
__global__ void prepBt_h(const float* __restrict__ W, __half* __restrict__ out,
                         int K, int N)
{
    __shared__ float tile[32][33];
    const int k0 = blockIdx.y * 32;
    const int n0 = blockIdx.x * 32;
    const int tx = threadIdx.x, ty = threadIdx.y;   // 32 x 8

    #pragma unroll
    for (int j = 0; j < 32; j += 8)
        tile[ty + j][tx] = W[(size_t)(k0 + ty + j) * N + n0 + tx];
    __syncthreads();

    #pragma unroll
    for (int j = 0; j < 32; j += 8)
        out[(size_t)(n0 + ty + j) * K + k0 + tx] = __float2half(tile[tx][ty + j]);
}

// ---------------------------------------------------------------------------
// Causal depthwise conv (k=4) + SiLU on the x half of xz
// ---------------------------------------------------------------------------
__global__ void conv_silu_kernel(const float* __restrict__ xz,
                                 const float* __restrict__ kw,
                                 const float* __restrict__ kb,
                                 float* __restrict__ out)
{
    int idx = blockIdx.x * blockDim.x + threadIdx.x;
    if (idx >= NTOK * DI) return;
    int d = idx & (DI - 1);
    int t = idx >> 11;
    int l = t & (L_ - 1);

    float acc = kb[d];
    #pragma unroll
    for (int i = 0; i < DC; i++) {
        int ls = l - (DC - 1) + i;
        if (ls >= 0)
            acc = fmaf(xz[(size_t)(t - (DC - 1) + i) * (2 * DI) + d],
                       kw[i * DI + d], acc);
    }
    out[idx] = silu_f(acc);
}

// ---------------------------------------------------------------------------
// x_dbl = xconv @ Wx   (NTOK x 96, K=2048). 4 token rows per block.
// ---------------------------------------------------------------------------
#define XR 4
__global__ void __launch_bounds__(96)
xdbl_kernel(const float* __restrict__ xc, const float* __restrict__ Wx,
            float* __restrict__ out)
{
    __shared__ float sh[XR][DI];
    const int row0 = blockIdx.x * XR;
    const int col  = threadIdx.x;
    for (int i = col; i < XR * DI; i += 96)
        ((float*)sh)[i] = xc[(size_t)row0 * DI + i];
    __syncthreads();

    float acc[XR] = {0.0f, 0.0f, 0.0f, 0.0f};
    #pragma unroll 8
    for (int k = 0; k < DI; k++) {
        float w = Wx[(size_t)k * XDBLW + col];
        #pragma unroll
        for (int r = 0; r < XR; r++)
            acc[r] = fmaf(sh[r][k], w, acc[r]);
    }
    #pragma unroll
    for (int r = 0; r < XR; r++)
        out[(size_t)(row0 + r) * XDBLW + col] = acc[r];
}

// ---------------------------------------------------------------------------
// Selective scan, deep-prefetch (PF=16 tokens of loads in flight).
// One thread per (channel, state-n); 16-lane groups reduce y over n.
// Writes gated output DIRECTLY as fp16 (A operand of the out-proj GEMM).
// ---------------------------------------------------------------------------
#define PF 16
__global__ void __launch_bounds__(256, 2)
scan_kernel(const float* __restrict__ delta, const float* __restrict__ u,
            const float* __restrict__ xdbl,  const float* __restrict__ xz,
            const float* __restrict__ A_log, const float* __restrict__ Dskip,
            __half* __restrict__ yH)
{
    const int tid = threadIdx.x;
    const int grp = tid >> 4;
    const int n   = tid & 15;
    const int c   = blockIdx.x * 16 + grp;
    const int b   = c >> 11;
    const int d   = c & (DI - 1);

    const float An = -__expf(A_log[d * NS + n]);
    const float Dd = Dskip[d];

    const float* drow = delta + (size_t)b * L_ * DI + d;
    const float* urow = u     + (size_t)b * L_ * DI + d;
    const float* zrow = xz    + (size_t)b * L_ * (2 * DI) + DI + d;
    const float* brow = xdbl  + (size_t)b * L_ * XDBLW + DTR + n;
    __half*      yrow = yH    + (size_t)b * L_ * DI + d;

    float pdv[PF], puv[PF], pBn[PF], pCn[PF];
    #pragma unroll
    for (int i = 0; i < PF; i++) {
        pdv[i] = drow[(size_t)i * DI];
        puv[i] = urow[(size_t)i * DI];
        pBn[i] = brow[(size_t)i * XDBLW];
        pCn[i] = brow[(size_t)i * XDBLW + NS];
    }

    float x = 0.0f;
    for (int l = 0; l < L_; l += PF) {
        #pragma unroll
        for (int i = 0; i < PF; i++) {
            const float dv = pdv[i], uv = puv[i], Bn = pBn[i], Cn = pCn[i];
            const int ln = l + i + PF;
            if (ln < L_) {
                pdv[i] = drow[(size_t)ln * DI];
                puv[i] = urow[(size_t)ln * DI];
                pBn[i] = brow[(size_t)ln * XDBLW];
                pCn[i] = brow[(size_t)ln * XDBLW + NS];
            }
            float dA = __expf(dv * An);
            x = fmaf(dA, x, dv * Bn * uv);
            float v = x * Cn;
            v += __shfl_xor_sync(0xffffffffu, v, 1, 16);
            v += __shfl_xor_sync(0xffffffffu, v, 2, 16);
            v += __shfl_xor_sync(0xffffffffu, v, 4, 16);
            v += __shfl_xor_sync(0xffffffffu, v, 8, 16);
            if (n == 0) {
                float zv = zrow[(size_t)(l + i) * (2 * DI)];
                yrow[(size_t)(l + i) * DI] =
                    __float2half((v + uv * Dd) * silu_f(zv));
            }
        }
    }
}

// ---------------------------------------------------------------------------
// Launch.  Launch #4 = GEMM1 (the slot ncu captures).
// ---------------------------------------------------------------------------
extern "C" void kernel_launch(void* const* d_in, const int* in_sizes, int n_in,
                              void* d_out, int out_size)
{
    const float* hs      = (const float*)d_in[0];
    const float* Win     = (const float*)d_in[1];
    const float* Wx      = (const float*)d_in[2];
    const float* Wdt     = (const float*)d_in[3];
    const float* dt_bias = (const float*)d_in[4];
    const float* Wout    = (const float*)d_in[5];
    const float* dwk     = (const float*)d_in[6];
    const float* dwb     = (const float*)d_in[7];
    const float* A_log   = (const float*)d_in[8];
    const float* Dskip   = (const float*)d_in[9];
    float* out = (float*)d_out;

    float  *xz, *xc, *xd, *dl;
    __half *hsH, *WinTH, *xdH, *WdtTH, *ybH, *WoutTH;
    cudaGetSymbolAddress((void**)&xz,     g_xz);
    cudaGetSymbolAddress((void**)&xc,     g_xconv);
    cudaGetSymbolAddress((void**)&xd,     g_xdbl);
    cudaGetSymbolAddress((void**)&dl,     g_delta);
    cudaGetSymbolAddress((void**)&hsH,    g_hsH);
    cudaGetSymbolAddress((void**)&WinTH,  g_WinTH);
    cudaGetSymbolAddress((void**)&xdH,    g_xdH);
    cudaGetSymbolAddress((void**)&WdtTH,  g_WdtTH);
    cudaGetSymbolAddress((void**)&ybH,    g_ybH);
    cudaGetSymbolAddress((void**)&WoutTH, g_WoutTH);

    static int smem_set = 0;
    if (!smem_set) {
        cudaFuncSetAttribute(tgemm_h<0, 128>,
            cudaFuncAttributeMaxDynamicSharedMemorySize, SMEM_G128);
        cudaFuncSetAttribute(tgemm_h<1, 128>,
            cudaFuncAttributeMaxDynamicSharedMemorySize, SMEM_G128);
        cudaFuncSetAttribute(tgemm_h<0, 64>,
            cudaFuncAttributeMaxDynamicSharedMemorySize, SMEM_G64);
        smem_set = 1;
    }

    // #1-#3: preps needed for GEMM1 (+ Wdt)
    prepA_h<<<(NTOK * DM / 2) / 256, 256>>>(hs, hsH, NTOK * DM / 2, 10, DM);
    prepBt_h<<<dim3((2 * DI) / 32, DM / 32), dim3(32, 8)>>>(Win, WinTH, DM, 2 * DI);
    prepBt_h<<<dim3(DI / 32, DTR / 32), dim3(32, 8)>>>(Wdt, WdtTH, DTR, DI);

    // #4: xz = hidden @ Win            (2048 x 4096, K=1024)  <- profiled slot
    tgemm_h<0, 128><<<dim3(4096 / 128, 2048 / 128), 256, SMEM_G128>>>(
        hsH, WinTH, xz, DM, 2 * DI, nullptr);

    // #5: depthwise causal conv + silu on x half
    conv_silu_kernel<<<(NTOK * DI + 255) / 256, 256>>>(xz, dwk, dwb, xc);

    // #6: x_dbl = xconv @ Wx           (2048 x 96, K=2048)
    xdbl_kernel<<<NTOK / XR, 96>>>(xc, Wx, xd);

    // #7-#8: delta = softplus(dt @ Wdt + dt_bias)   (2048 x 2048, K=64)
    prepA_h<<<(NTOK * DTR / 2) / 256, 256>>>(xd, xdH, NTOK * DTR / 2, 6, XDBLW);
    tgemm_h<1, 128><<<dim3(2048 / 128, 2048 / 128), 256, SMEM_G128>>>(
        xdH, WdtTH, dl, DTR, DI, dt_bias);

    // #9: prep Wout
    prepBt_h<<<dim3(DM / 32, DI / 32), dim3(32, 8)>>>(Wout, WoutTH, DI, DM);

    // #10: selective scan (+skip, *silu(z)) -> fp16 directly
    scan_kernel<<<(B_ * DI) / 16, 256>>>(dl, xc, xd, xz, A_log, Dskip, ybH);

    // #11: out = y @ Wout              (2048 x 1024, K=2048), 128x64 tiles
    tgemm_h<0, 64><<<dim3(1024 / 64, 2048 / 128), 256, SMEM_G64>>>(
        ybH, WoutTH, out, DI, DM, nullptr);
}

// round 14
// speedup vs baseline: 1.7001x; 1.0786x over previous
#include <cuda_runtime.h>
#include <cuda_fp16.h>
#include <math.h>
#include <stdint.h>

// Problem dims (fixed by the dataset)
#define B_    2
#define L_    1024
#define DM    1024
#define DI    2048
#define NS    16
#define DTR   64
#define DC    4
#define NTOK  (B_ * L_)      // 2048 tokens
#define XDBLW 96             // DT_RANK + 2*N (logical)
#define XDP   128            // padded x_dbl row stride

// ---------------------------------------------------------------------------
// Scratch (static __device__ arrays -- allocation-free per harness rules)
// ---------------------------------------------------------------------------
__device__ float  g_xz   [(size_t)NTOK * 2 * DI];
__device__ float  g_xconv[(size_t)NTOK * DI];
__device__ float  g_xdbl [(size_t)NTOK * XDP];    // [dt(64) | B(16) | C(16) | pad]
__device__ float  g_delta[(size_t)NTOK * DI];
// fp16 operands for the tensor-core GEMMs
__device__ __half g_hsH   [(size_t)NTOK * DM];
__device__ __half g_WinTH [(size_t)(2 * DI) * DM];
__device__ __half g_xcH   [(size_t)NTOK * DI];    // conv output fp16 (A of xdbl GEMM)
__device__ __half g_WxTH  [(size_t)XDP * DI];     // Wx^T padded to 128 rows
__device__ __half g_xdH   [(size_t)NTOK * DTR];   // dt cols fp16 (A of delta GEMM)
__device__ __half g_WdtTH [(size_t)DI * DTR];
__device__ __half g_ybH   [(size_t)NTOK * DI];
__device__ __half g_WoutTH[(size_t)DM * DI];

// ---------------------------------------------------------------------------
// Helpers
// ---------------------------------------------------------------------------
__device__ __forceinline__ float silu_f(float x) {
    return x / (1.0f + __expf(-x));
}
__device__ __forceinline__ float softplus_f(float x) {
    return (x > 20.0f) ? x : log1pf(__expf(x));
}

#define CPA16(smp, gp) \
    asm volatile("cp.async.cg.shared.global [%0], [%1], 16;\n" :: "r"(smp), "l"(gp))
#define CPA_COMMIT()  asm volatile("cp.async.commit_group;\n")
#define CPA_WAIT0()   asm volatile("cp.async.wait_group 0;\n" ::: "memory")

__device__ __forceinline__ uint32_t smem_u32(const void* p) {
    uint32_t a;
    asm("{ .reg .u64 t; cvta.to.shared.u64 t, %1; cvt.u32.u64 %0, t; }"
        : "=r"(a) : "l"(p));
    return a;
}

__device__ __forceinline__ void mma_f16(float* c,
                                        uint32_t a0, uint32_t a1, uint32_t a2, uint32_t a3,
                                        uint32_t b0, uint32_t b1) {
    asm volatile(
        "mma.sync.aligned.m16n8k16.row.col.f32.f16.f16.f32 "
        "{%0,%1,%2,%3}, {%4,%5,%6,%7}, {%8,%9}, {%0,%1,%2,%3};\n"
        : "+f"(c[0]), "+f"(c[1]), "+f"(c[2]), "+f"(c[3])
        : "r"(a0), "r"(a1), "r"(a2), "r"(a3), "r"(b0), "r"(b1));
}

#define LDSM_X4(r0, r1, r2, r3, addr)                                        \
    asm volatile("ldmatrix.sync.aligned.m8n8.x4.shared.b16 {%0,%1,%2,%3}, [%4];" \
                 : "=r"(r0), "=r"(r1), "=r"(r2), "=r"(r3) : "r"(addr))

// ---------------------------------------------------------------------------
// FP16 tensor-core GEMM: C[M,N] = A[M,K] @ Bt[N,K]^T, fp32 accumulate.
// Block tile 128xBN (BN=128 or 64), BK=64 per barrier (4 k16 sub-steps),
// 2-stage cp.async buffer, copy of tile i+1 overlaps compute of tile i.
// Requires K multiple of 64.
// EPI: 0 plain, 1 softplus(acc+bias[col]), 2 fp32 store + fp16 dt cols->xdH
// ---------------------------------------------------------------------------
#define ROWH 72   // 64 k-halves + 8 pad -> 144B row stride, LDSM conflict-free
#define NSTG 2

template <int EPI, int BN>
__global__ void __launch_bounds__(256)
tgemm_h(const __half* __restrict__ A, const __half* __restrict__ Bt,
        float* __restrict__ C, int K, int ldc, const float* __restrict__ bias,
        __half* __restrict__ auxH)
{
    constexpr int MI = (BN == 128) ? 4 : 2;
    constexpr uint32_t ASTG = 128 * ROWH * 2;
    constexpr uint32_t BSTG = (uint32_t)BN * ROWH * 2;

    extern __shared__ __align__(16) char dsm[];
    const uint32_t sA0 = smem_u32(dsm);
    const uint32_t sB0 = sA0 + NSTG * ASTG;

    const int tid  = threadIdx.x;
    const int bm   = blockIdx.y * 128;
    const int bn   = blockIdx.x * BN;
    const int lane = tid & 31;
    const int wid  = tid >> 5;
    const int wm   = (BN == 128) ? (wid & 1) * 64 : (wid & 3) * 32;
    const int wn   = (BN == 128) ? (wid >> 1) * 32 : (wid >> 2) * 32;
    const int g    = lane >> 2;
    const int t    = lane & 3;

    // staging: rows sr / sr+64, 16B chunks kc and kc+4 (of 8 per row)
    const int sr = tid >> 2;             // 0..63
    const int kc = (tid & 3) * 8;        // halves: chunks at kc and kc+32

    const __half* Ag0 = A + (size_t)(bm + sr) * K + kc;
    const __half* Ag1 = A + (size_t)(bm + sr + 64) * K + kc;
    const __half* Bg0 = Bt + (size_t)(bn + sr) * K + kc;
    const __half* Bg1 = (BN == 128) ? Bt + (size_t)(bn + sr + 64) * K + kc : Bg0;

    const uint32_t R64 = 64 * ROWH * 2;
    const uint32_t stA = sA0 + (uint32_t)(sr * ROWH + kc) * 2;
    const uint32_t stB = sB0 + (uint32_t)(sr * ROWH + kc) * 2;

#define STAGE(kt, bf)                                                  \
    {                                                                  \
        CPA16(stA + (bf) * ASTG,            Ag0 + (size_t)(kt) * 64);  \
        CPA16(stA + (bf) * ASTG + 64,       Ag0 + (size_t)(kt) * 64 + 32); \
        CPA16(stA + (bf) * ASTG + R64,      Ag1 + (size_t)(kt) * 64);  \
        CPA16(stA + (bf) * ASTG + R64 + 64, Ag1 + (size_t)(kt) * 64 + 32); \
        CPA16(stB + (bf) * BSTG,            Bg0 + (size_t)(kt) * 64);  \
        CPA16(stB + (bf) * BSTG + 64,       Bg0 + (size_t)(kt) * 64 + 32); \
        if (BN == 128) {                                               \
            CPA16(stB + (bf) * BSTG + R64,      Bg1 + (size_t)(kt) * 64); \
            CPA16(stB + (bf) * BSTG + R64 + 64, Bg1 + (size_t)(kt) * 64 + 32); \
        }                                                              \
        CPA_COMMIT();                                                  \
    }

    // ldmatrix lane-address bases
    const int li = lane & 7;
    const int q  = lane >> 3;
    const uint32_t aBase = sA0
        + (uint32_t)(((wm + li + 8 * (q & 1)) * ROWH + 8 * (q >> 1)) * 2);
    const uint32_t bBase = sB0
        + (uint32_t)(((wn + li + 8 * (q >> 1)) * ROWH + 8 * (q & 1)) * 2);

    float acc[MI][4][4];
    #pragma unroll
    for (int mi = 0; mi < MI; mi++)
        #pragma unroll
        for (int ni = 0; ni < 4; ni++)
            #pragma unroll
            for (int p = 0; p < 4; p++) acc[mi][ni][p] = 0.0f;

    const int nIter = K / 64;
    STAGE(0, 0);

    int buf = 0;
    for (int it = 0; it < nIter; ++it) {
        CPA_WAIT0();
        __syncthreads();
        if (it + 1 < nIter) STAGE(it + 1, buf ^ 1);

        const uint32_t ab  = aBase + buf * ASTG;
        const uint32_t bb_ = bBase + buf * BSTG;

        #pragma unroll
        for (int s = 0; s < 4; s++) {
            uint32_t a[MI][4], bv[2][4];
            #pragma unroll
            for (int mi = 0; mi < MI; mi++)
                LDSM_X4(a[mi][0], a[mi][1], a[mi][2], a[mi][3],
                        ab + (uint32_t)((mi * 16 * ROWH + s * 16) * 2));
            #pragma unroll
            for (int p = 0; p < 2; p++)
                LDSM_X4(bv[p][0], bv[p][1], bv[p][2], bv[p][3],
                        bb_ + (uint32_t)((p * 16 * ROWH + s * 16) * 2));
            #pragma unroll
            for (int mi = 0; mi < MI; mi++)
                #pragma unroll
                for (int ni = 0; ni < 4; ni++) {
                    const int p = ni >> 1, o = (ni & 1) * 2;
                    mma_f16(acc[mi][ni], a[mi][0], a[mi][1], a[mi][2], a[mi][3],
                            bv[p][o], bv[p][o + 1]);
                }
        }
        buf ^= 1;
    }

    #pragma unroll
    for (int mi = 0; mi < MI; mi++) {
        #pragma unroll
        for (int ni = 0; ni < 4; ni++) {
            const int row = bm + wm + mi * 16 + g;
            const int col = bn + wn + ni * 8 + 2 * t;
            float v0 = acc[mi][ni][0], v1 = acc[mi][ni][1];
            float v2 = acc[mi][ni][2], v3 = acc[mi][ni][3];
            if (EPI == 1) {
                const float c0 = bias[col], c1 = bias[col + 1];
                v0 = softplus_f(v0 + c0);
                v1 = softplus_f(v1 + c1);
                v2 = softplus_f(v2 + c0);
                v3 = softplus_f(v3 + c1);
            }
            *(float2*)(C + (size_t)row * ldc + col)       = make_float2(v0, v1);
            *(float2*)(C + (size_t)(row + 8) * ldc + col) = make_float2(v2, v3);
            if (EPI == 2 && col < DTR) {
                *(__half2*)(auxH + (size_t)row * DTR + col) =
                    __floats2half2_rn(v0, v1);
                *(__half2*)(auxH + (size_t)(row + 8) * DTR + col) =
                    __floats2half2_rn(v2, v3);
            }
        }
    }
#undef STAGE
}

#define SMEM_G128 (NSTG * (128 + 128) * ROWH * 2)   // 73728
#define SMEM_G64  (NSTG * (128 + 64) * ROWH * 2)    // 55296

// ---------------------------------------------------------------------------
// Prep A -> half (pairs)
// ---------------------------------------------------------------------------
__global__ void prepA_h(const float* __restrict__ in, __half* __restrict__ out,
                        int MKhalf, int kbits, int ldin)
{
    int idx = blockIdx.x * blockDim.x + threadIdx.x;
    if (idx >= MKhalf) return;
    int e  = idx * 2;
    int m  = e >> kbits;
    int k  = e & ((1 << kbits) - 1);
    const float* p = in + (size_t)m * ldin + k;
    ((__half2*)out)[idx] = __floats2half2_rn(p[0], p[1]);
}

// ---------------------------------------------------------------------------
// Prep B^T -> half with optional row padding:
//   out[n][k] = (n < N) ? half(W[k][n]) : 0, for n in [0, Npad)
// W is (K, N) row-major.  Grid covers Npad/32 x K/32.
// ---------------------------------------------------------------------------
__global__ void prepBt_h(const float* __restrict__ W, __half* __restrict__ out,
                         int K, int N)
{
    __shared__ float tile[32][33];
    const int k0 = blockIdx.y * 32;
    const int n0 = blockIdx.x * 32;
    const int tx = threadIdx.x, ty = threadIdx.y;   // 32 x 8

    #pragma unroll
    for (int j = 0; j < 32; j += 8) {
        const int n = n0 + tx;
        tile[ty + j][tx] = (n < N) ? W[(size_t)(k0 + ty + j) * N + n] : 0.0f;
    }
    __syncthreads();

    #pragma unroll
    for (int j = 0; j < 32; j += 8)
        out[(size_t)(n0 + ty + j) * K + k0 + tx] = __float2half(tile[tx][ty + j]);
}

// ---------------------------------------------------------------------------
// Causal depthwise conv (k=4) + SiLU; writes fp32 (scan u) and fp16 (GEMM A)
// ---------------------------------------------------------------------------
__global__ void conv_silu_kernel(const float* __restrict__ xz,
                                 const float* __restrict__ kw,
                                 const float* __restrict__ kb,
                                 float* __restrict__ outF,
                                 __half* __restrict__ outH)
{
    int idx = blockIdx.x * blockDim.x + threadIdx.x;
    if (idx >= NTOK * DI) return;
    int d = idx & (DI - 1);
    int t = idx >> 11;
    int l = t & (L_ - 1);

    float acc = kb[d];
    #pragma unroll
    for (int i = 0; i < DC; i++) {
        int ls = l - (DC - 1) + i;
        if (ls >= 0)
            acc = fmaf(xz[(size_t)(t - (DC - 1) + i) * (2 * DI) + d],
                       kw[i * DI + d], acc);
    }
    float v = silu_f(acc);
    outF[idx] = v;
    outH[idx] = __float2half(v);
}

// ---------------------------------------------------------------------------
// Selective scan, deep-prefetch (PF=16). 16-lane groups reduce y over n.
// Writes gated output DIRECTLY as fp16 (A operand of the out-proj GEMM).
// ---------------------------------------------------------------------------
#define PF 16
__global__ void __launch_bounds__(256, 2)
scan_kernel(const float* __restrict__ delta, const float* __restrict__ u,
            const float* __restrict__ xdbl,  const float* __restrict__ xz,
            const float* __restrict__ A_log, const float* __restrict__ Dskip,
            __half* __restrict__ yH)
{
    const int tid = threadIdx.x;
    const int grp = tid >> 4;
    const int n   = tid & 15;
    const int c   = blockIdx.x * 16 + grp;
    const int b   = c >> 11;
    const int d   = c & (DI - 1);

    const float An = -__expf(A_log[d * NS + n]);
    const float Dd = Dskip[d];

    const float* drow = delta + (size_t)b * L_ * DI + d;
    const float* urow = u     + (size_t)b * L_ * DI + d;
    const float* zrow = xz    + (size_t)b * L_ * (2 * DI) + DI + d;
    const float* brow = xdbl  + (size_t)b * L_ * XDP + DTR + n;
    __half*      yrow = yH    + (size_t)b * L_ * DI + d;

    float pdv[PF], puv[PF], pBn[PF], pCn[PF];
    #pragma unroll
    for (int i = 0; i < PF; i++) {
        pdv[i] = drow[(size_t)i * DI];
        puv[i] = urow[(size_t)i * DI];
        pBn[i] = brow[(size_t)i * XDP];
        pCn[i] = brow[(size_t)i * XDP + NS];
    }

    float x = 0.0f;
    for (int l = 0; l < L_; l += PF) {
        #pragma unroll
        for (int i = 0; i < PF; i++) {
            const float dv = pdv[i], uv = puv[i], Bn = pBn[i], Cn = pCn[i];
            const int ln = l + i + PF;
            if (ln < L_) {
                pdv[i] = drow[(size_t)ln * DI];
                puv[i] = urow[(size_t)ln * DI];
                pBn[i] = brow[(size_t)ln * XDP];
                pCn[i] = brow[(size_t)ln * XDP + NS];
            }
            float dA = __expf(dv * An);
            x = fmaf(dA, x, dv * Bn * uv);
            float v = x * Cn;
            v += __shfl_xor_sync(0xffffffffu, v, 1, 16);
            v += __shfl_xor_sync(0xffffffffu, v, 2, 16);
            v += __shfl_xor_sync(0xffffffffu, v, 4, 16);
            v += __shfl_xor_sync(0xffffffffu, v, 8, 16);
            if (n == 0) {
                float zv = zrow[(size_t)(l + i) * (2 * DI)];
                yrow[(size_t)(l + i) * DI] =
                    __float2half((v + uv * Dd) * silu_f(zv));
            }
        }
    }
}

// ---------------------------------------------------------------------------
// Launch
// ---------------------------------------------------------------------------
extern "C" void kernel_launch(void* const* d_in, const int* in_sizes, int n_in,
                              void* d_out, int out_size)
{
    const float* hs      = (const float*)d_in[0];
    const float* Win     = (const float*)d_in[1];
    const float* Wx      = (const float*)d_in[2];
    const float* Wdt     = (const float*)d_in[3];
    const float* dt_bias = (const float*)d_in[4];
    const float* Wout    = (const float*)d_in[5];
    const float* dwk     = (const float*)d_in[6];
    const float* dwb     = (const float*)d_in[7];
    const float* A_log   = (const float*)d_in[8];
    const float* Dskip   = (const float*)d_in[9];
    float* out = (float*)d_out;

    float  *xz, *xc, *xd, *dl;
    __half *hsH, *WinTH, *xcH, *WxTH, *xdH, *WdtTH, *ybH, *WoutTH;
    cudaGetSymbolAddress((void**)&xz,     g_xz);
    cudaGetSymbolAddress((void**)&xc,     g_xconv);
    cudaGetSymbolAddress((void**)&xd,     g_xdbl);
    cudaGetSymbolAddress((void**)&dl,     g_delta);
    cudaGetSymbolAddress((void**)&hsH,    g_hsH);
    cudaGetSymbolAddress((void**)&WinTH,  g_WinTH);
    cudaGetSymbolAddress((void**)&xcH,    g_xcH);
    cudaGetSymbolAddress((void**)&WxTH,   g_WxTH);
    cudaGetSymbolAddress((void**)&xdH,    g_xdH);
    cudaGetSymbolAddress((void**)&WdtTH,  g_WdtTH);
    cudaGetSymbolAddress((void**)&ybH,    g_ybH);
    cudaGetSymbolAddress((void**)&WoutTH, g_WoutTH);

    static int smem_set = 0;
    if (!smem_set) {
        cudaFuncSetAttribute(tgemm_h<0, 128>,
            cudaFuncAttributeMaxDynamicSharedMemorySize, SMEM_G128);
        cudaFuncSetAttribute(tgemm_h<1, 128>,
            cudaFuncAttributeMaxDynamicSharedMemorySize, SMEM_G128);
        cudaFuncSetAttribute(tgemm_h<0, 64>,
            cudaFuncAttributeMaxDynamicSharedMemorySize, SMEM_G64);
        cudaFuncSetAttribute(tgemm_h<2, 64>,
            cudaFuncAttributeMaxDynamicSharedMemorySize, SMEM_G64);
        smem_set = 1;
    }

    // #1-#3: preps for GEMM1 (+ Wdt)
    prepA_h<<<(NTOK * DM / 2) / 256, 256>>>(hs, hsH, NTOK * DM / 2, 10, DM);
    prepBt_h<<<dim3((2 * DI) / 32, DM / 32), dim3(32, 8)>>>(Win, WinTH, DM, 2 * DI);
    prepBt_h<<<dim3(DI / 32, DTR / 32), dim3(32, 8)>>>(Wdt, WdtTH, DTR, DI);

    // #4: xz = hidden @ Win            (2048 x 4096, K=1024)  <- profiled slot
    tgemm_h<0, 128><<<dim3(4096 / 128, 2048 / 128), 256, SMEM_G128>>>(
        hsH, WinTH, xz, DM, 2 * DI, nullptr, nullptr);

    // #5: depthwise causal conv + silu -> fp32 + fp16
    conv_silu_kernel<<<(NTOK * DI + 255) / 256, 256>>>(xz, dwk, dwb, xc, xcH);

    // #6: prep Wx^T padded to 128 rows
    prepBt_h<<<dim3(XDP / 32, DI / 32), dim3(32, 8)>>>(Wx, WxTH, DI, XDBLW);

    // #7: x_dbl = xconv @ Wx  (2048 x 128pad, K=2048) + dt cols fp16 -> xdH
    tgemm_h<2, 64><<<dim3(XDP / 64, 2048 / 128), 256, SMEM_G64>>>(
        xcH, WxTH, xd, DI, XDP, nullptr, xdH);

    // #8: delta = softplus(dt @ Wdt + dt_bias)   (2048 x 2048, K=64)
    tgemm_h<1, 128><<<dim3(2048 / 128, 2048 / 128), 256, SMEM_G128>>>(
        xdH, WdtTH, dl, DTR, DI, dt_bias, nullptr);

    // #9: prep Wout
    prepBt_h<<<dim3(DM / 32, DI / 32), dim3(32, 8)>>>(Wout, WoutTH, DI, DM);

    // #10: selective scan (+skip, *silu(z)) -> fp16 directly
    scan_kernel<<<(B_ * DI) / 16, 256>>>(dl, xc, xd, xz, A_log, Dskip, ybH);

    // #11: out = y @ Wout              (2048 x 1024, K=2048), 128x64 tiles
    tgemm_h<0, 64><<<dim3(1024 / 64, 2048 / 128), 256, SMEM_G64>>>(
        ybH, WoutTH, out, DI, DM, nullptr, nullptr);
}

// round 16
// speedup vs baseline: 3.3006x; 1.9414x over previous
#include <cuda_runtime.h>
#include <cuda_fp16.h>
#include <math.h>
#include <stdint.h>

// Problem dims (fixed by the dataset)
#define B_    2
#define L_    1024
#define DM    1024
#define DI    2048
#define NS    16
#define DTR   64
#define DC    4
#define NTOK  (B_ * L_)      // 2048 tokens
#define XDBLW 96             // DT_RANK + 2*N (logical)
#define XDP   128            // padded x_dbl row stride
#define NCHAN (B_ * DI)      // 4096 channels
#define CH    32             // tokens per scan chunk
#define NCH   (L_ / CH)      // 32 chunks
#define NGRP  (NCHAN * NCH)  // 131072 scan groups

// ---------------------------------------------------------------------------
// Scratch (static __device__ arrays -- allocation-free per harness rules)
// ---------------------------------------------------------------------------
__device__ float  g_xz   [(size_t)NTOK * 2 * DI];
__device__ float  g_xconv[(size_t)NTOK * DI];
__device__ float  g_xdbl [(size_t)NTOK * XDP];    // [dt(64) | B(16) | C(16) | pad]
__device__ float  g_delta[(size_t)NTOK * DI];
// chunked-scan summaries
__device__ float  g_prodA[(size_t)NGRP * NS];
__device__ float  g_xend [(size_t)NGRP * NS];
__device__ float  g_xin  [(size_t)NGRP * NS];
// fp16 operands for the tensor-core GEMMs
__device__ __half g_hsH   [(size_t)NTOK * DM];
__device__ __half g_WinTH [(size_t)(2 * DI) * DM];
__device__ __half g_WxTH  [(size_t)XDP * DI];
__device__ __half g_xcH   [(size_t)NTOK * DI];
__device__ __half g_xdH   [(size_t)NTOK * DTR];
__device__ __half g_WdtTH [(size_t)DI * DTR];
__device__ __half g_ybH   [(size_t)NTOK * DI];
__device__ __half g_WoutTH[(size_t)DM * DI];

// ---------------------------------------------------------------------------
// Helpers
// ---------------------------------------------------------------------------
__device__ __forceinline__ float silu_f(float x) {
    return x / (1.0f + __expf(-x));
}
__device__ __forceinline__ float softplus_f(float x) {
    return (x > 20.0f) ? x : log1pf(__expf(x));
}

#define CPA16(smp, gp) \
    asm volatile("cp.async.cg.shared.global [%0], [%1], 16;\n" :: "r"(smp), "l"(gp))
#define CPA_COMMIT()  asm volatile("cp.async.commit_group;\n")
#define CPA_WAIT0()   asm volatile("cp.async.wait_group 0;\n" ::: "memory")

__device__ __forceinline__ uint32_t smem_u32(const void* p) {
    uint32_t a;
    asm("{ .reg .u64 t; cvta.to.shared.u64 t, %1; cvt.u32.u64 %0, t; }"
        : "=r"(a) : "l"(p));
    return a;
}

__device__ __forceinline__ void mma_f16(float* c,
                                        uint32_t a0, uint32_t a1, uint32_t a2, uint32_t a3,
                                        uint32_t b0, uint32_t b1) {
    asm volatile(
        "mma.sync.aligned.m16n8k16.row.col.f32.f16.f16.f32 "
        "{%0,%1,%2,%3}, {%4,%5,%6,%7}, {%8,%9}, {%0,%1,%2,%3};\n"
        : "+f"(c[0]), "+f"(c[1]), "+f"(c[2]), "+f"(c[3])
        : "r"(a0), "r"(a1), "r"(a2), "r"(a3), "r"(b0), "r"(b1));
}

#define LDSM_X4(r0, r1, r2, r3, addr)                                        \
    asm volatile("ldmatrix.sync.aligned.m8n8.x4.shared.b16 {%0,%1,%2,%3}, [%4];" \
                 : "=r"(r0), "=r"(r1), "=r"(r2), "=r"(r3) : "r"(addr))

// ---------------------------------------------------------------------------
// FP16 tensor-core GEMM (unchanged from round 14): C = A @ Bt^T, fp32 accum.
// Block tile 128xBN (BN=128 or 64), BK=64 per barrier, 2-stage cp.async.
// EPI: 0 plain, 1 softplus(acc+bias[col]), 2 fp32 store + fp16 dt cols->auxH
// ---------------------------------------------------------------------------
#define ROWH 72
#define NSTG 2

template <int EPI, int BN>
__global__ void __launch_bounds__(256)
tgemm_h(const __half* __restrict__ A, const __half* __restrict__ Bt,
        float* __restrict__ C, int K, int ldc, const float* __restrict__ bias,
        __half* __restrict__ auxH)
{
    constexpr int MI = (BN == 128) ? 4 : 2;
    constexpr uint32_t ASTG = 128 * ROWH * 2;
    constexpr uint32_t BSTG = (uint32_t)BN * ROWH * 2;

    extern __shared__ __align__(16) char dsm[];
    const uint32_t sA0 = smem_u32(dsm);
    const uint32_t sB0 = sA0 + NSTG * ASTG;

    const int tid  = threadIdx.x;
    const int bm   = blockIdx.y * 128;
    const int bn   = blockIdx.x * BN;
    const int lane = tid & 31;
    const int wid  = tid >> 5;
    const int wm   = (BN == 128) ? (wid & 1) * 64 : (wid & 3) * 32;
    const int wn   = (BN == 128) ? (wid >> 1) * 32 : (wid >> 2) * 32;
    const int g    = lane >> 2;
    const int t    = lane & 3;

    const int sr = tid >> 2;
    const int kc = (tid & 3) * 8;

    const __half* Ag0 = A + (size_t)(bm + sr) * K + kc;
    const __half* Ag1 = A + (size_t)(bm + sr + 64) * K + kc;
    const __half* Bg0 = Bt + (size_t)(bn + sr) * K + kc;
    const __half* Bg1 = (BN == 128) ? Bt + (size_t)(bn + sr + 64) * K + kc : Bg0;

    const uint32_t R64 = 64 * ROWH * 2;
    const uint32_t stA = sA0 + (uint32_t)(sr * ROWH + kc) * 2;
    const uint32_t stB = sB0 + (uint32_t)(sr * ROWH + kc) * 2;

#define STAGE(kt, bf)                                                  \
    {                                                                  \
        CPA16(stA + (bf) * ASTG,            Ag0 + (size_t)(kt) * 64);  \
        CPA16(stA + (bf) * ASTG + 64,       Ag0 + (size_t)(kt) * 64 + 32); \
        CPA16(stA + (bf) * ASTG + R64,      Ag1 + (size_t)(kt) * 64);  \
        CPA16(stA + (bf) * ASTG + R64 + 64, Ag1 + (size_t)(kt) * 64 + 32); \
        CPA16(stB + (bf) * BSTG,            Bg0 + (size_t)(kt) * 64);  \
        CPA16(stB + (bf) * BSTG + 64,       Bg0 + (size_t)(kt) * 64 + 32); \
        if (BN == 128) {                                               \
            CPA16(stB + (bf) * BSTG + R64,      Bg1 + (size_t)(kt) * 64); \
            CPA16(stB + (bf) * BSTG + R64 + 64, Bg1 + (size_t)(kt) * 64 + 32); \
        }                                                              \
        CPA_COMMIT();                                                  \
    }

    const int li = lane & 7;
    const int q  = lane >> 3;
    const uint32_t aBase = sA0
        + (uint32_t)(((wm + li + 8 * (q & 1)) * ROWH + 8 * (q >> 1)) * 2);
    const uint32_t bBase = sB0
        + (uint32_t)(((wn + li + 8 * (q >> 1)) * ROWH + 8 * (q & 1)) * 2);

    float acc[MI][4][4];
    #pragma unroll
    for (int mi = 0; mi < MI; mi++)
        #pragma unroll
        for (int ni = 0; ni < 4; ni++)
            #pragma unroll
            for (int p = 0; p < 4; p++) acc[mi][ni][p] = 0.0f;

    const int nIter = K / 64;
    STAGE(0, 0);

    int buf = 0;
    for (int it = 0; it < nIter; ++it) {
        CPA_WAIT0();
        __syncthreads();
        if (it + 1 < nIter) STAGE(it + 1, buf ^ 1);

        const uint32_t ab  = aBase + buf * ASTG;
        const uint32_t bb_ = bBase + buf * BSTG;

        #pragma unroll
        for (int s = 0; s < 4; s++) {
            uint32_t a[MI][4], bv[2][4];
            #pragma unroll
            for (int mi = 0; mi < MI; mi++)
                LDSM_X4(a[mi][0], a[mi][1], a[mi][2], a[mi][3],
                        ab + (uint32_t)((mi * 16 * ROWH + s * 16) * 2));
            #pragma unroll
            for (int p = 0; p < 2; p++)
                LDSM_X4(bv[p][0], bv[p][1], bv[p][2], bv[p][3],
                        bb_ + (uint32_t)((p * 16 * ROWH + s * 16) * 2));
            #pragma unroll
            for (int mi = 0; mi < MI; mi++)
                #pragma unroll
                for (int ni = 0; ni < 4; ni++) {
                    const int p = ni >> 1, o = (ni & 1) * 2;
                    mma_f16(acc[mi][ni], a[mi][0], a[mi][1], a[mi][2], a[mi][3],
                            bv[p][o], bv[p][o + 1]);
                }
        }
        buf ^= 1;
    }

    #pragma unroll
    for (int mi = 0; mi < MI; mi++) {
        #pragma unroll
        for (int ni = 0; ni < 4; ni++) {
            const int row = bm + wm + mi * 16 + g;
            const int col = bn + wn + ni * 8 + 2 * t;
            float v0 = acc[mi][ni][0], v1 = acc[mi][ni][1];
            float v2 = acc[mi][ni][2], v3 = acc[mi][ni][3];
            if (EPI == 1) {
                const float c0 = bias[col], c1 = bias[col + 1];
                v0 = softplus_f(v0 + c0);
                v1 = softplus_f(v1 + c1);
                v2 = softplus_f(v2 + c0);
                v3 = softplus_f(v3 + c1);
            }
            *(float2*)(C + (size_t)row * ldc + col)       = make_float2(v0, v1);
            *(float2*)(C + (size_t)(row + 8) * ldc + col) = make_float2(v2, v3);
            if (EPI == 2 && col < DTR) {
                *(__half2*)(auxH + (size_t)row * DTR + col) =
                    __floats2half2_rn(v0, v1);
                *(__half2*)(auxH + (size_t)(row + 8) * DTR + col) =
                    __floats2half2_rn(v2, v3);
            }
        }
    }
#undef STAGE
}

#define SMEM_G128 (NSTG * (128 + 128) * ROWH * 2)
#define SMEM_G64  (NSTG * (128 + 64) * ROWH * 2)

// ---------------------------------------------------------------------------
// Fused prep: all fp16 operand preparation in ONE launch (range dispatch).
//   blocks [0, 4096)        : hs -> hsH (elementwise pairs)
//   blocks [4096, 8192)     : Win^T   (K=DM,   N=2*DI, grid 128 wide)
//   blocks [8192, 8320)     : Wdt^T   (K=DTR,  N=DI,   grid 64 wide)
//   blocks [8320, 10368)    : Wout^T  (K=DI,   N=DM,   grid 32 wide)
//   blocks [10368, 10624)   : Wx^T    (K=DI,   N=96 pad 128, grid 4 wide)
// ---------------------------------------------------------------------------
__device__ __forceinline__ void transp_body(const float* __restrict__ W,
                                            __half* __restrict__ out,
                                            int K, int N, int n0, int k0, int tid)
{
    __shared__ float tile[32][33];
    const int tx = tid & 31, ty = tid >> 5;   // 32 x 8
    #pragma unroll
    for (int j = 0; j < 32; j += 8) {
        const int n = n0 + tx;
        tile[ty + j][tx] = (n < N) ? W[(size_t)(k0 + ty + j) * N + n] : 0.0f;
    }
    __syncthreads();
    #pragma unroll
    for (int j = 0; j < 32; j += 8)
        out[(size_t)(n0 + ty + j) * K + k0 + tx] = __float2half(tile[tx][ty + j]);
}

__global__ void __launch_bounds__(256)
prep_all(const float* __restrict__ hs,   __half* __restrict__ hsH,
         const float* __restrict__ Win,  __half* __restrict__ WinTH,
         const float* __restrict__ Wdt,  __half* __restrict__ WdtTH,
         const float* __restrict__ Wout, __half* __restrict__ WoutTH,
         const float* __restrict__ Wx,   __half* __restrict__ WxTH)
{
    const int blk = blockIdx.x;
    const int tid = threadIdx.x;

    if (blk < 4096) {
        int idx = blk * 256 + tid;                 // pair index, hs is dense
        const float* p = hs + (size_t)idx * 2;
        ((__half2*)hsH)[idx] = __floats2half2_rn(p[0], p[1]);
    } else if (blk < 8192) {
        int b = blk - 4096;
        transp_body(Win, WinTH, DM, 2 * DI, (b & 127) * 32, (b >> 7) * 32, tid);
    } else if (blk < 8320) {
        int b = blk - 8192;
        transp_body(Wdt, WdtTH, DTR, DI, (b & 63) * 32, (b >> 6) * 32, tid);
    } else if (blk < 10368) {
        int b = blk - 8320;
        transp_body(Wout, WoutTH, DI, DM, (b & 31) * 32, (b >> 5) * 32, tid);
    } else {
        int b = blk - 10368;
        transp_body(Wx, WxTH, DI, XDBLW, (b & 3) * 32, (b >> 2) * 32, tid);
    }
}
#define PREP_BLOCKS 10624

// ---------------------------------------------------------------------------
// Causal depthwise conv (k=4) + SiLU; writes fp32 (scan u) and fp16 (GEMM A)
// ---------------------------------------------------------------------------
__global__ void conv_silu_kernel(const float* __restrict__ xz,
                                 const float* __restrict__ kw,
                                 const float* __restrict__ kb,
                                 float* __restrict__ outF,
                                 __half* __restrict__ outH)
{
    int idx = blockIdx.x * blockDim.x + threadIdx.x;
    if (idx >= NTOK * DI) return;
    int d = idx & (DI - 1);
    int t = idx >> 11;
    int l = t & (L_ - 1);

    float acc = kb[d];
    #pragma unroll
    for (int i = 0; i < DC; i++) {
        int ls = l - (DC - 1) + i;
        if (ls >= 0)
            acc = fmaf(xz[(size_t)(t - (DC - 1) + i) * (2 * DI) + d],
                       kw[i * DI + d], acc);
    }
    float v = silu_f(acc);
    outF[idx] = v;
    outH[idx] = __float2half(v);
}

// ---------------------------------------------------------------------------
// Chunked selective scan.  Group g = chunk * NCHAN + channel; 16 lanes = n.
// Pass 1: per-chunk local scan (x0 = 0) -> (prod a, x_end)
// ---------------------------------------------------------------------------
__global__ void __launch_bounds__(256)
scan_p1(const float* __restrict__ delta, const float* __restrict__ u,
        const float* __restrict__ xdbl,  const float* __restrict__ A_log,
        float* __restrict__ prodA, float* __restrict__ xend)
{
    const int tid = threadIdx.x;
    const int grp = tid >> 4;
    const int n   = tid & 15;
    const int g   = blockIdx.x * 16 + grp;
    const int cc  = g & (NCHAN - 1);          // channel
    const int ck  = g >> 12;                  // chunk
    const int b   = cc >> 11;
    const int d   = cc & (DI - 1);
    const int l0  = ck * CH;

    const float An = -__expf(A_log[d * NS + n]);

    const float* drow = delta + (size_t)b * L_ * DI + (size_t)l0 * DI + d;
    const float* urow = u     + (size_t)b * L_ * DI + (size_t)l0 * DI + d;
    const float* brow = xdbl  + (size_t)b * L_ * XDP + (size_t)l0 * XDP + DTR + n;

    float x = 0.0f, prod = 1.0f;
    #pragma unroll 8
    for (int i = 0; i < CH; ++i) {
        float dv = drow[(size_t)i * DI];
        float uv = urow[(size_t)i * DI];
        float Bn = brow[(size_t)i * XDP];
        float a  = __expf(dv * An);
        prod *= a;
        x = fmaf(a, x, dv * Bn * uv);
    }
    prodA[(size_t)g * NS + n] = prod;
    xend [(size_t)g * NS + n] = x;
}

// ---------------------------------------------------------------------------
// Pass 2: serial combine over chunks -> true entry state per (channel, n, chunk)
// ---------------------------------------------------------------------------
__global__ void __launch_bounds__(256)
scan_p2(const float* __restrict__ prodA, const float* __restrict__ xend,
        float* __restrict__ xin)
{
    const int idx = blockIdx.x * 256 + threadIdx.x;   // 65536 = channel*16+n
    const int cc  = idx >> 4;
    const int n   = idx & 15;

    float pa[NCH], xe[NCH];
    #pragma unroll
    for (int c = 0; c < NCH; ++c) {
        size_t o = ((size_t)c * NCHAN + cc) * NS + n;
        pa[c] = prodA[o];
        xe[c] = xend[o];
    }
    float x = 0.0f;
    #pragma unroll
    for (int c = 0; c < NCH; ++c) {
        xin[((size_t)c * NCHAN + cc) * NS + n] = x;
        x = fmaf(pa[c], x, xe[c]);
    }
}

// ---------------------------------------------------------------------------
// Pass 3: re-run each chunk from its true entry state; emit gated fp16 y.
// ---------------------------------------------------------------------------
__global__ void __launch_bounds__(256)
scan_p3(const float* __restrict__ delta, const float* __restrict__ u,
        const float* __restrict__ xdbl,  const float* __restrict__ xz,
        const float* __restrict__ A_log, const float* __restrict__ Dskip,
        const float* __restrict__ xin,   __half* __restrict__ yH)
{
    const int tid = threadIdx.x;
    const int grp = tid >> 4;
    const int n   = tid & 15;
    const int g   = blockIdx.x * 16 + grp;
    const int cc  = g & (NCHAN - 1);
    const int ck  = g >> 12;
    const int b   = cc >> 11;
    const int d   = cc & (DI - 1);
    const int l0  = ck * CH;

    const float An = -__expf(A_log[d * NS + n]);
    const float Dd = Dskip[d];

    const float* drow = delta + (size_t)b * L_ * DI + (size_t)l0 * DI + d;
    const float* urow = u     + (size_t)b * L_ * DI + (size_t)l0 * DI + d;
    const float* zrow = xz    + (size_t)b * L_ * (2 * DI) + (size_t)l0 * (2 * DI) + DI + d;
    const float* brow = xdbl  + (size_t)b * L_ * XDP + (size_t)l0 * XDP + DTR + n;
    __half*      yrow = yH    + (size_t)b * L_ * DI + (size_t)l0 * DI + d;

    float x = xin[(size_t)g * NS + n];

    #pragma unroll 8
    for (int i = 0; i < CH; ++i) {
        float dv = drow[(size_t)i * DI];
        float uv = urow[(size_t)i * DI];
        float Bn = brow[(size_t)i * XDP];
        float Cn = brow[(size_t)i * XDP + NS];

        float a = __expf(dv * An);
        x = fmaf(a, x, dv * Bn * uv);

        float v = x * Cn;
        v += __shfl_xor_sync(0xffffffffu, v, 1, 16);
        v += __shfl_xor_sync(0xffffffffu, v, 2, 16);
        v += __shfl_xor_sync(0xffffffffu, v, 4, 16);
        v += __shfl_xor_sync(0xffffffffu, v, 8, 16);

        if (n == 0) {
            float zv = zrow[(size_t)i * (2 * DI)];
            yrow[(size_t)i * DI] = __float2half((v + uv * Dd) * silu_f(zv));
        }
    }
}

// ---------------------------------------------------------------------------
// Launch.  9 nodes; slot #4 (index 3) = xdbl GEMM (profiled).
// ---------------------------------------------------------------------------
extern "C" void kernel_launch(void* const* d_in, const int* in_sizes, int n_in,
                              void* d_out, int out_size)
{
    const float* hs      = (const float*)d_in[0];
    const float* Win     = (const float*)d_in[1];
    const float* Wx      = (const float*)d_in[2];
    const float* Wdt     = (const float*)d_in[3];
    const float* dt_bias = (const float*)d_in[4];
    const float* Wout    = (const float*)d_in[5];
    const float* dwk     = (const float*)d_in[6];
    const float* dwb     = (const float*)d_in[7];
    const float* A_log   = (const float*)d_in[8];
    const float* Dskip   = (const float*)d_in[9];
    float* out = (float*)d_out;

    float  *xz, *xc, *xd, *dl, *prodA, *xend, *xin;
    __half *hsH, *WinTH, *WxTH, *xcH, *xdH, *WdtTH, *ybH, *WoutTH;
    cudaGetSymbolAddress((void**)&xz,     g_xz);
    cudaGetSymbolAddress((void**)&xc,     g_xconv);
    cudaGetSymbolAddress((void**)&xd,     g_xdbl);
    cudaGetSymbolAddress((void**)&dl,     g_delta);
    cudaGetSymbolAddress((void**)&prodA,  g_prodA);
    cudaGetSymbolAddress((void**)&xend,   g_xend);
    cudaGetSymbolAddress((void**)&xin,    g_xin);
    cudaGetSymbolAddress((void**)&hsH,    g_hsH);
    cudaGetSymbolAddress((void**)&WinTH,  g_WinTH);
    cudaGetSymbolAddress((void**)&WxTH,   g_WxTH);
    cudaGetSymbolAddress((void**)&xcH,    g_xcH);
    cudaGetSymbolAddress((void**)&xdH,    g_xdH);
    cudaGetSymbolAddress((void**)&WdtTH,  g_WdtTH);
    cudaGetSymbolAddress((void**)&ybH,    g_ybH);
    cudaGetSymbolAddress((void**)&WoutTH, g_WoutTH);

    static int smem_set = 0;
    if (!smem_set) {
        cudaFuncSetAttribute(tgemm_h<0, 128>,
            cudaFuncAttributeMaxDynamicSharedMemorySize, SMEM_G128);
        cudaFuncSetAttribute(tgemm_h<1, 128>,
            cudaFuncAttributeMaxDynamicSharedMemorySize, SMEM_G128);
        cudaFuncSetAttribute(tgemm_h<0, 64>,
            cudaFuncAttributeMaxDynamicSharedMemorySize, SMEM_G64);
        cudaFuncSetAttribute(tgemm_h<2, 64>,
            cudaFuncAttributeMaxDynamicSharedMemorySize, SMEM_G64);
        smem_set = 1;
    }

    // #1: fused operand prep (all fp16 conversions/transposes)
    prep_all<<<PREP_BLOCKS, 256>>>(hs, hsH, Win, WinTH, Wdt, WdtTH,
                                   Wout, WoutTH, Wx, WxTH);

    // #2: xz = hidden @ Win            (2048 x 4096, K=1024)
    tgemm_h<0, 128><<<dim3(4096 / 128, 2048 / 128), 256, SMEM_G128>>>(
        hsH, WinTH, xz, DM, 2 * DI, nullptr, nullptr);

    // #3: depthwise causal conv + silu -> fp32 + fp16
    conv_silu_kernel<<<(NTOK * DI + 255) / 256, 256>>>(xz, dwk, dwb, xc, xcH);

    // #4: x_dbl = xconv @ Wx  (2048 x 128pad, K=2048)  <- profiled slot
    tgemm_h<2, 64><<<dim3(XDP / 64, 2048 / 128), 256, SMEM_G64>>>(
        xcH, WxTH, xd, DI, XDP, nullptr, xdH);

    // #5: delta = softplus(dt @ Wdt + dt_bias)   (2048 x 2048, K=64)
    tgemm_h<1, 128><<<dim3(2048 / 128, 2048 / 128), 256, SMEM_G128>>>(
        xdH, WdtTH, dl, DTR, DI, dt_bias, nullptr);

    // #6-#8: time-parallel chunked selective scan
    scan_p1<<<NGRP / 16, 256>>>(dl, xc, xd, A_log, prodA, xend);
    scan_p2<<<(NCHAN * NS) / 256, 256>>>(prodA, xend, xin);
    scan_p3<<<NGRP / 16, 256>>>(dl, xc, xd, xz, A_log, Dskip, xin, ybH);

    // #9: out = y @ Wout               (2048 x 1024, K=2048), 128x64 tiles
    tgemm_h<0, 64><<<dim3(1024 / 64, 2048 / 128), 256, SMEM_G64>>>(
        ybH, WoutTH, out, DI, DM, nullptr, nullptr);
}